// round 1
// baseline (speedup 1.0000x reference)
#include <cuda_runtime.h>
#include <math.h>

#define B_SZ   32768
#define NW     30
#define VOCAB  32000
#define WD     300
#define CH     400
#define AD     200

// ---------------- scratch (static device globals; no allocation) ----------------
__device__ float g_M[WD * 600];          // B-matrix for Q gemm: [i][k*200+a]
__device__ float g_cvb[AD];              // conv_b @ v + vb
__device__ float g_Q[VOCAB * 600];       // [tok][k*200+a]   (76.8 MB)
__device__ float g_aT[NW * B_SZ];        // scores transposed: [n][b]
__device__ float g_mx[NW];
__device__ float g_isum[NW];
__device__ float g_G[(size_t)B_SZ * 900];// [b][k*300+i]     (118 MB)
__device__ float g_salpha[B_SZ];
__device__ float g_Wc2[900 * CH];        // [k*300+i][o]

// ---------------- prep: M[i][k*200+a] = sum_o conv_w[o,i,k] * v[o,a] ----------------
__global__ void prep_M_kernel(const float* __restrict__ conv_w, const float* __restrict__ v)
{
    int idx = blockIdx.x * blockDim.x + threadIdx.x;
    if (idx >= WD * 600) return;
    int i = idx / 600;
    int r = idx % 600;
    int k = r / 200;
    int a = r % 200;
    float s = 0.f;
    #pragma unroll 4
    for (int o = 0; o < CH; o++)
        s += conv_w[o * (WD * 3) + i * 3 + k] * v[o * AD + a];
    g_M[idx] = s;
}

// cvb[a] = vb[a] + sum_o conv_b[o]*v[o,a]
__global__ void prep_cvb_kernel(const float* __restrict__ conv_b,
                                const float* __restrict__ v,
                                const float* __restrict__ vb)
{
    int a = blockIdx.x * blockDim.x + threadIdx.x;
    if (a >= AD) return;
    float s = vb[a];
    for (int o = 0; o < CH; o++) s += conv_b[o] * v[o * AD + a];
    g_cvb[a] = s;
}

// Wc2[k*300+i][o] = conv_w[o,i,k]
__global__ void prep_Wc2_kernel(const float* __restrict__ conv_w)
{
    int idx = blockIdx.x * blockDim.x + threadIdx.x;
    if (idx >= 900 * CH) return;
    int row = idx / CH;          // k*300 + i
    int o   = idx % CH;
    int k = row / WD;
    int i = row % WD;
    g_Wc2[idx] = conv_w[o * (WD * 3) + i * 3 + k];
}

// ---------------- generic fp32 SGEMM: C[M,N] = A[M,K] @ B[K,N] (+ rs[m]*bias[n]) ----------------
// BM=128, BN=128, BK=8, 256 threads, 8x8 microtile. M must be a multiple of 128.
__global__ __launch_bounds__(256)
void sgemm_kernel(const float* __restrict__ A, const float* __restrict__ B,
                  float* __restrict__ C, int M, int N, int K,
                  const float* __restrict__ rs, const float* __restrict__ bias)
{
    __shared__ float As[8][128];
    __shared__ float Bs[8][128];

    const int tid = threadIdx.x;
    const int m0 = blockIdx.y * 128;
    const int n0 = blockIdx.x * 128;
    const int tx = tid & 15;     // 0..15 (cols)
    const int ty = tid >> 4;     // 0..15 (rows)

    const int arow = tid >> 1;           // 0..127
    const int acol = (tid & 1) * 4;      // 0 or 4
    const int brow = tid >> 5;           // 0..7
    const int bcol = (tid & 31) * 4;     // 0..124

    float acc[8][8];
    #pragma unroll
    for (int i = 0; i < 8; i++)
        #pragma unroll
        for (int j = 0; j < 8; j++) acc[i][j] = 0.f;

    for (int k0 = 0; k0 < K; k0 += 8) {
        // --- load A tile (128 x 8), store transposed As[k][m] ---
        float4 av;
        {
            const size_t base = (size_t)(m0 + arow) * K + k0 + acol;
            if (k0 + acol + 3 < K) {
                av = *reinterpret_cast<const float4*>(A + base);
            } else {
                av.x = (k0 + acol + 0 < K) ? A[base + 0] : 0.f;
                av.y = (k0 + acol + 1 < K) ? A[base + 1] : 0.f;
                av.z = (k0 + acol + 2 < K) ? A[base + 2] : 0.f;
                av.w = (k0 + acol + 3 < K) ? A[base + 3] : 0.f;
            }
        }
        As[acol + 0][arow] = av.x;
        As[acol + 1][arow] = av.y;
        As[acol + 2][arow] = av.z;
        As[acol + 3][arow] = av.w;

        // --- load B tile (8 x 128) ---
        float4 bv = make_float4(0.f, 0.f, 0.f, 0.f);
        {
            const int kb = k0 + brow;
            if (kb < K) {
                const size_t base = (size_t)kb * N + n0 + bcol;
                if (n0 + bcol + 3 < N) {
                    bv = *reinterpret_cast<const float4*>(B + base);
                } else {
                    if (n0 + bcol + 0 < N) bv.x = B[base + 0];
                    if (n0 + bcol + 1 < N) bv.y = B[base + 1];
                    if (n0 + bcol + 2 < N) bv.z = B[base + 2];
                    if (n0 + bcol + 3 < N) bv.w = B[base + 3];
                }
            }
        }
        *reinterpret_cast<float4*>(&Bs[brow][bcol]) = bv;

        __syncthreads();

        #pragma unroll
        for (int kk = 0; kk < 8; kk++) {
            float af[8], bf[8];
            float4 a0 = *reinterpret_cast<const float4*>(&As[kk][ty * 8 + 0]);
            float4 a1 = *reinterpret_cast<const float4*>(&As[kk][ty * 8 + 4]);
            float4 b0 = *reinterpret_cast<const float4*>(&Bs[kk][tx * 8 + 0]);
            float4 b1 = *reinterpret_cast<const float4*>(&Bs[kk][tx * 8 + 4]);
            af[0]=a0.x; af[1]=a0.y; af[2]=a0.z; af[3]=a0.w;
            af[4]=a1.x; af[5]=a1.y; af[6]=a1.z; af[7]=a1.w;
            bf[0]=b0.x; bf[1]=b0.y; bf[2]=b0.z; bf[3]=b0.w;
            bf[4]=b1.x; bf[5]=b1.y; bf[6]=b1.z; bf[7]=b1.w;
            #pragma unroll
            for (int i = 0; i < 8; i++)
                #pragma unroll
                for (int j = 0; j < 8; j++)
                    acc[i][j] = fmaf(af[i], bf[j], acc[i][j]);
        }
        __syncthreads();
    }

    // --- epilogue ---
    #pragma unroll
    for (int i = 0; i < 8; i++) {
        const int row = m0 + ty * 8 + i;
        const float r = rs ? rs[row] : 0.f;
        #pragma unroll
        for (int j = 0; j < 8; j++) {
            const int col = n0 + tx * 8 + j;
            if (col < N) {
                float val = acc[i][j];
                if (bias) val += r * bias[col];
                C[(size_t)row * N + col] = val;
            }
        }
    }
}

// ---------------- scores: a[b,n] = q . tanh(cvb + Q0[t_{n-1}] + Q1[t_n] + Q2[t_{n+1}]) ----------------
// one warp per b; 8 warps per block
__global__ __launch_bounds__(256)
void score_kernel(const int* __restrict__ tok, const float* __restrict__ qv)
{
    __shared__ float sq[AD];
    __shared__ float scvb[AD];
    __shared__ int stok[8][NW];

    const int tid = threadIdx.x;
    const int wid = tid >> 5;
    const int lane = tid & 31;
    const int b = blockIdx.x * 8 + wid;

    if (tid < AD) { sq[tid] = qv[tid]; scvb[tid] = g_cvb[tid]; }
    if (lane < NW) stok[wid][lane] = tok[b * NW + lane];
    __syncthreads();

    for (int n = 0; n < NW; n++) {
        const int tc  = stok[wid][n];
        const int tp  = (n > 0)      ? stok[wid][n - 1] : -1;
        const int tn2 = (n < NW - 1) ? stok[wid][n + 1] : -1;
        const float* qc = g_Q + (size_t)tc * 600 + 200;   // k=1 slice
        float s = 0.f;
        for (int a = lane; a < AD; a += 32) {
            float h = scvb[a] + qc[a];
            if (tp  >= 0) h += g_Q[(size_t)tp  * 600 + a];         // k=0 slice
            if (tn2 >= 0) h += g_Q[(size_t)tn2 * 600 + 400 + a];   // k=2 slice
            s += tanhf(h) * sq[a];
        }
        #pragma unroll
        for (int off = 16; off; off >>= 1)
            s += __shfl_down_sync(0xffffffffu, s, off);
        if (lane == 0) g_aT[n * B_SZ + b] = s;
    }
}

// ---------------- softmax stats over batch axis, one block per n ----------------
__global__ __launch_bounds__(1024)
void softmax_stats_kernel()
{
    __shared__ float red[1024];
    const int n = blockIdx.x;
    const int tid = threadIdx.x;
    const float* row = g_aT + (size_t)n * B_SZ;

    float mx = -INFINITY;
    for (int b = tid; b < B_SZ; b += 1024) mx = fmaxf(mx, row[b]);
    red[tid] = mx;
    __syncthreads();
    for (int s = 512; s > 0; s >>= 1) {
        if (tid < s) red[tid] = fmaxf(red[tid], red[tid + s]);
        __syncthreads();
    }
    mx = red[0];
    __syncthreads();

    float sum = 0.f;
    for (int b = tid; b < B_SZ; b += 1024) sum += expf(row[b] - mx);
    red[tid] = sum;
    __syncthreads();
    for (int s = 512; s > 0; s >>= 1) {
        if (tid < s) red[tid] += red[tid + s];
        __syncthreads();
    }
    if (tid == 0) { g_mx[n] = mx; g_isum[n] = 1.f / red[0]; }
}

// ---------------- build G[b,k,i] = sum_n alpha[b,n] * E[b,n+k-1,i] ----------------
// one block per b, 320 threads (i = 0..299 active for the weighted sums)
__global__ __launch_bounds__(320)
void gbuild_kernel(const int* __restrict__ tok, const float* __restrict__ emb)
{
    __shared__ float sal[NW];
    __shared__ int stok[NW];
    const int b = blockIdx.x;
    const int tid = threadIdx.x;

    if (tid < NW) {
        sal[tid] = expf(g_aT[tid * B_SZ + b] - g_mx[tid]) * g_isum[tid];
        stok[tid] = tok[b * NW + tid];
    }
    __syncthreads();

    if (tid == 0) {
        float s = 0.f;
        #pragma unroll
        for (int n = 0; n < NW; n++) s += sal[n];
        g_salpha[b] = s;
    }

    const int i = tid;
    if (i < WD) {
        float g0 = 0.f, g1 = 0.f, g2 = 0.f;
        #pragma unroll 5
        for (int m = 0; m < NW; m++) {
            const float em = emb[(size_t)stok[m] * WD + i];
            g1 += sal[m] * em;
            if (m < NW - 1) g0 += sal[m + 1] * em;
            if (m > 0)      g2 += sal[m - 1] * em;
        }
        float* gp = g_G + (size_t)b * 900;
        gp[i]       = g0;
        gp[300 + i] = g1;
        gp[600 + i] = g2;
    }
}

// ---------------- launch ----------------
extern "C" void kernel_launch(void* const* d_in, const int* in_sizes, int n_in,
                              void* d_out, int out_size)
{
    const int*   tok    = (const int*)  d_in[0];   // [32768,30]
    const float* emb    = (const float*)d_in[1];   // [32000,300]
    const float* conv_w = (const float*)d_in[2];   // [400,300,3]
    const float* conv_b = (const float*)d_in[3];   // [400]
    const float* v      = (const float*)d_in[4];   // [400,200]
    const float* vb     = (const float*)d_in[5];   // [200]
    const float* q      = (const float*)d_in[6];   // [200,1]
    float* out = (float*)d_out;                    // [32768,400]

    // device-global scratch pointers (resolved at compile time inside kernels;
    // here we need raw addresses for the GEMM arguments)
    float *pM, *pQ, *pG, *pWc2, *psal;
    cudaGetSymbolAddress((void**)&pM,   g_M);
    cudaGetSymbolAddress((void**)&pQ,   g_Q);
    cudaGetSymbolAddress((void**)&pG,   g_G);
    cudaGetSymbolAddress((void**)&pWc2, g_Wc2);
    cudaGetSymbolAddress((void**)&psal, g_salpha);

    // 1. prep small matrices
    prep_M_kernel<<<(WD * 600 + 255) / 256, 256>>>(conv_w, v);
    prep_cvb_kernel<<<1, 256>>>(conv_b, v, vb);
    prep_Wc2_kernel<<<(900 * CH + 255) / 256, 256>>>(conv_w);

    // 2. Q = emb @ M : [32000,300] x [300,600]
    {
        dim3 grid((600 + 127) / 128, VOCAB / 128);
        sgemm_kernel<<<grid, 256>>>(emb, pM, pQ, VOCAB, 600, WD, nullptr, nullptr);
    }

    // 3. attention scores
    score_kernel<<<B_SZ / 8, 256>>>(tok, q);

    // 4. softmax stats over batch axis
    softmax_stats_kernel<<<NW, 1024>>>();

    // 5. build G and sum-alpha
    gbuild_kernel<<<B_SZ, 320>>>(tok, emb);

    // 6. e = G @ Wc2 + salpha * conv_b : [32768,900] x [900,400]
    {
        dim3 grid((CH + 127) / 128, B_SZ / 128);
        sgemm_kernel<<<grid, 256>>>(pG, pWc2, out, B_SZ, CH, 900, psal, conv_b);
    }
}

// round 2
// speedup vs baseline: 1.2606x; 1.2606x over previous
#include <cuda_runtime.h>
#include <math.h>

#define B_SZ   32768
#define NW     30
#define VOCAB  32000
#define WD     300
#define CH     400
#define AD     200

// ---------------- scratch (static device globals; no allocation) ----------------
__device__ float g_M[WD * 600];          // B-matrix for Q gemm: [i][k*200+a]
__device__ float g_cvb[AD];              // conv_b @ v + vb
__device__ float g_Q[VOCAB * 600];       // [tok][k*200+a]   (76.8 MB)
__device__ float g_aT[NW * B_SZ];        // scores transposed: [n][b]
__device__ float g_mx[NW];
__device__ float g_isum[NW];
__device__ float g_G[(size_t)B_SZ * 900];// [b][k*300+i]     (118 MB)
__device__ float g_salpha[B_SZ];
__device__ float g_Wc2[900 * CH];        // [k*300+i][o]

// ---------------- prep: M[i][k*200+a] = sum_o conv_w[o,i,k] * v[o,a] ----------------
__global__ void prep_M_kernel(const float* __restrict__ conv_w, const float* __restrict__ v)
{
    int idx = blockIdx.x * blockDim.x + threadIdx.x;
    if (idx >= WD * 600) return;
    int i = idx / 600;
    int r = idx % 600;
    int k = r / 200;
    int a = r % 200;
    float s = 0.f;
    #pragma unroll 4
    for (int o = 0; o < CH; o++)
        s += conv_w[o * (WD * 3) + i * 3 + k] * v[o * AD + a];
    g_M[idx] = s;
}

// cvb[a] = vb[a] + sum_o conv_b[o]*v[o,a]
__global__ void prep_cvb_kernel(const float* __restrict__ conv_b,
                                const float* __restrict__ v,
                                const float* __restrict__ vb)
{
    int a = blockIdx.x * blockDim.x + threadIdx.x;
    if (a >= AD) return;
    float s = vb[a];
    for (int o = 0; o < CH; o++) s += conv_b[o] * v[o * AD + a];
    g_cvb[a] = s;
}

// Wc2[k*300+i][o] = conv_w[o,i,k]
__global__ void prep_Wc2_kernel(const float* __restrict__ conv_w)
{
    int idx = blockIdx.x * blockDim.x + threadIdx.x;
    if (idx >= 900 * CH) return;
    int row = idx / CH;          // k*300 + i
    int o   = idx % CH;
    int k = row / WD;
    int i = row % WD;
    g_Wc2[idx] = conv_w[o * (WD * 3) + i * 3 + k];
}

// ---------------- double-buffered fp32 SGEMM: C[M,N] = A[M,K] @ B[K,N] (+ rs[m]*bias[n]) ----
// BM=128, BN=128, BK=8, 256 threads, 8x8 microtile, register-prefetch pipeline.
// M must be a multiple of 128.
__global__ __launch_bounds__(256, 2)
void sgemm_kernel(const float* __restrict__ A, const float* __restrict__ B,
                  float* __restrict__ C, int M, int N, int K,
                  const float* __restrict__ rs, const float* __restrict__ bias)
{
    __shared__ float As[2][8][128];
    __shared__ float Bs[2][8][128];

    const int tid = threadIdx.x;
    const int m0 = blockIdx.y * 128;
    const int n0 = blockIdx.x * 128;
    const int tx = tid & 15;     // 0..15 (cols)
    const int ty = tid >> 4;     // 0..15 (rows)

    const int arow = tid >> 1;           // 0..127
    const int acol = (tid & 1) * 4;      // 0 or 4
    const int brow = tid >> 5;           // 0..7
    const int bcol = (tid & 31) * 4;     // 0..124

    float acc[8][8];
    #pragma unroll
    for (int i = 0; i < 8; i++)
        #pragma unroll
        for (int j = 0; j < 8; j++) acc[i][j] = 0.f;

    // ---- guarded gmem loads for one k-panel ----
    auto loadA = [&](int k0) -> float4 {
        float4 av;
        const size_t base = (size_t)(m0 + arow) * K + k0 + acol;
        if (k0 + acol + 3 < K) {
            av = *reinterpret_cast<const float4*>(A + base);
        } else {
            av.x = (k0 + acol + 0 < K) ? A[base + 0] : 0.f;
            av.y = (k0 + acol + 1 < K) ? A[base + 1] : 0.f;
            av.z = (k0 + acol + 2 < K) ? A[base + 2] : 0.f;
            av.w = (k0 + acol + 3 < K) ? A[base + 3] : 0.f;
        }
        return av;
    };
    auto loadB = [&](int k0) -> float4 {
        float4 bv = make_float4(0.f, 0.f, 0.f, 0.f);
        const int kb = k0 + brow;
        if (kb < K) {
            const size_t base = (size_t)kb * N + n0 + bcol;
            if (n0 + bcol + 3 < N) {
                bv = *reinterpret_cast<const float4*>(B + base);
            } else {
                if (n0 + bcol + 0 < N) bv.x = B[base + 0];
                if (n0 + bcol + 1 < N) bv.y = B[base + 1];
                if (n0 + bcol + 2 < N) bv.z = B[base + 2];
                if (n0 + bcol + 3 < N) bv.w = B[base + 3];
            }
        }
        return bv;
    };

    // ---- preload panel 0 into buffer 0 ----
    {
        float4 av = loadA(0);
        float4 bv = loadB(0);
        As[0][acol + 0][arow] = av.x;
        As[0][acol + 1][arow] = av.y;
        As[0][acol + 2][arow] = av.z;
        As[0][acol + 3][arow] = av.w;
        *reinterpret_cast<float4*>(&Bs[0][brow][bcol]) = bv;
    }
    __syncthreads();

    const int nIter = (K + 7) / 8;
    int buf = 0;

    for (int it = 0; it < nIter; ++it) {
        const int k0n = (it + 1) * 8;
        const bool hasNext = (k0n < K);
        float4 av_n, bv_n;
        if (hasNext) {                 // issue gmem loads early
            av_n = loadA(k0n);
            bv_n = loadB(k0n);
        }

        // ---- compute on current buffer ----
        #pragma unroll
        for (int kk = 0; kk < 8; kk++) {
            float af[8], bf[8];
            float4 a0 = *reinterpret_cast<const float4*>(&As[buf][kk][ty * 8 + 0]);
            float4 a1 = *reinterpret_cast<const float4*>(&As[buf][kk][ty * 8 + 4]);
            float4 b0 = *reinterpret_cast<const float4*>(&Bs[buf][kk][tx * 8 + 0]);
            float4 b1 = *reinterpret_cast<const float4*>(&Bs[buf][kk][tx * 8 + 4]);
            af[0]=a0.x; af[1]=a0.y; af[2]=a0.z; af[3]=a0.w;
            af[4]=a1.x; af[5]=a1.y; af[6]=a1.z; af[7]=a1.w;
            bf[0]=b0.x; bf[1]=b0.y; bf[2]=b0.z; bf[3]=b0.w;
            bf[4]=b1.x; bf[5]=b1.y; bf[6]=b1.z; bf[7]=b1.w;
            #pragma unroll
            for (int i = 0; i < 8; i++)
                #pragma unroll
                for (int j = 0; j < 8; j++)
                    acc[i][j] = fmaf(af[i], bf[j], acc[i][j]);
        }

        // ---- stash prefetched panel into the other buffer ----
        if (hasNext) {
            As[buf ^ 1][acol + 0][arow] = av_n.x;
            As[buf ^ 1][acol + 1][arow] = av_n.y;
            As[buf ^ 1][acol + 2][arow] = av_n.z;
            As[buf ^ 1][acol + 3][arow] = av_n.w;
            *reinterpret_cast<float4*>(&Bs[buf ^ 1][brow][bcol]) = bv_n;
        }
        __syncthreads();
        buf ^= 1;
    }

    // --- epilogue ---
    #pragma unroll
    for (int i = 0; i < 8; i++) {
        const int row = m0 + ty * 8 + i;
        const float r = rs ? rs[row] : 0.f;
        #pragma unroll
        for (int j = 0; j < 8; j++) {
            const int col = n0 + tx * 8 + j;
            if (col < N) {
                float val = acc[i][j];
                if (bias) val += r * bias[col];
                C[(size_t)row * N + col] = val;
            }
        }
    }
}

// ---------------- scores: a[b,n] = q . tanh(cvb + Q0[t_{n-1}] + Q1[t_n] + Q2[t_{n+1}]) ----------------
// one warp per b; 8 warps per block; float4 gathers
__global__ __launch_bounds__(256)
void score_kernel(const int* __restrict__ tok, const float* __restrict__ qv)
{
    __shared__ float4 sq[AD / 4];       // 50
    __shared__ float4 scvb[AD / 4];     // 50
    __shared__ int stok[8][NW];

    const int tid = threadIdx.x;
    const int wid = tid >> 5;
    const int lane = tid & 31;
    const int b = blockIdx.x * 8 + wid;

    if (tid < AD / 4) {
        sq[tid]   = reinterpret_cast<const float4*>(qv)[tid];
        scvb[tid] = reinterpret_cast<const float4*>(g_cvb)[tid];
    }
    if (lane < NW) stok[wid][lane] = tok[b * NW + lane];
    __syncthreads();

    for (int n = 0; n < NW; n++) {
        const int tc  = stok[wid][n];
        const int tp  = (n > 0)      ? stok[wid][n - 1] : -1;
        const int tn2 = (n < NW - 1) ? stok[wid][n + 1] : -1;
        const float4* q1 = reinterpret_cast<const float4*>(g_Q + (size_t)tc * 600 + 200);
        const float4* q0 = (tp  >= 0) ? reinterpret_cast<const float4*>(g_Q + (size_t)tp  * 600)       : nullptr;
        const float4* q2 = (tn2 >= 0) ? reinterpret_cast<const float4*>(g_Q + (size_t)tn2 * 600 + 400) : nullptr;

        float s = 0.f;
        #pragma unroll
        for (int a4 = lane; a4 < AD / 4; a4 += 32) {
            float4 h = scvb[a4];
            float4 c = q1[a4];
            h.x += c.x; h.y += c.y; h.z += c.z; h.w += c.w;
            if (q0) { float4 p = q0[a4]; h.x += p.x; h.y += p.y; h.z += p.z; h.w += p.w; }
            if (q2) { float4 p = q2[a4]; h.x += p.x; h.y += p.y; h.z += p.z; h.w += p.w; }
            float4 qq = sq[a4];
            s += tanhf(h.x) * qq.x + tanhf(h.y) * qq.y + tanhf(h.z) * qq.z + tanhf(h.w) * qq.w;
        }
        #pragma unroll
        for (int off = 16; off; off >>= 1)
            s += __shfl_down_sync(0xffffffffu, s, off);
        if (lane == 0) g_aT[n * B_SZ + b] = s;
    }
}

// ---------------- softmax stats over batch axis, one block per n ----------------
__global__ __launch_bounds__(1024)
void softmax_stats_kernel()
{
    __shared__ float red[1024];
    const int n = blockIdx.x;
    const int tid = threadIdx.x;
    const float* row = g_aT + (size_t)n * B_SZ;

    float mx = -INFINITY;
    for (int b = tid; b < B_SZ; b += 1024) mx = fmaxf(mx, row[b]);
    red[tid] = mx;
    __syncthreads();
    for (int s = 512; s > 0; s >>= 1) {
        if (tid < s) red[tid] = fmaxf(red[tid], red[tid + s]);
        __syncthreads();
    }
    mx = red[0];
    __syncthreads();

    float sum = 0.f;
    for (int b = tid; b < B_SZ; b += 1024) sum += expf(row[b] - mx);
    red[tid] = sum;
    __syncthreads();
    for (int s = 512; s > 0; s >>= 1) {
        if (tid < s) red[tid] += red[tid + s];
        __syncthreads();
    }
    if (tid == 0) { g_mx[n] = mx; g_isum[n] = 1.f / red[0]; }
}

// ---------------- build G[b,k,i] = sum_n alpha[b,n] * E[b,n+k-1,i] ----------------
// one block per b, 320 threads (i = 0..299 active for the weighted sums)
__global__ __launch_bounds__(320)
void gbuild_kernel(const int* __restrict__ tok, const float* __restrict__ emb)
{
    __shared__ float sal[NW];
    __shared__ int stok[NW];
    const int b = blockIdx.x;
    const int tid = threadIdx.x;

    if (tid < NW) {
        sal[tid] = expf(g_aT[tid * B_SZ + b] - g_mx[tid]) * g_isum[tid];
        stok[tid] = tok[b * NW + tid];
    }
    __syncthreads();

    if (tid == 0) {
        float s = 0.f;
        #pragma unroll
        for (int n = 0; n < NW; n++) s += sal[n];
        g_salpha[b] = s;
    }

    const int i = tid;
    if (i < WD) {
        float g0 = 0.f, g1 = 0.f, g2 = 0.f;
        #pragma unroll 5
        for (int m = 0; m < NW; m++) {
            const float em = emb[(size_t)stok[m] * WD + i];
            g1 += sal[m] * em;
            if (m < NW - 1) g0 += sal[m + 1] * em;
            if (m > 0)      g2 += sal[m - 1] * em;
        }
        float* gp = g_G + (size_t)b * 900;
        gp[i]       = g0;
        gp[300 + i] = g1;
        gp[600 + i] = g2;
    }
}

// ---------------- launch ----------------
extern "C" void kernel_launch(void* const* d_in, const int* in_sizes, int n_in,
                              void* d_out, int out_size)
{
    const int*   tok    = (const int*)  d_in[0];   // [32768,30]
    const float* emb    = (const float*)d_in[1];   // [32000,300]
    const float* conv_w = (const float*)d_in[2];   // [400,300,3]
    const float* conv_b = (const float*)d_in[3];   // [400]
    const float* v      = (const float*)d_in[4];   // [400,200]
    const float* vb     = (const float*)d_in[5];   // [200]
    const float* q      = (const float*)d_in[6];   // [200,1]
    float* out = (float*)d_out;                    // [32768,400]

    float *pM, *pQ, *pG, *pWc2, *psal;
    cudaGetSymbolAddress((void**)&pM,   g_M);
    cudaGetSymbolAddress((void**)&pQ,   g_Q);
    cudaGetSymbolAddress((void**)&pG,   g_G);
    cudaGetSymbolAddress((void**)&pWc2, g_Wc2);
    cudaGetSymbolAddress((void**)&psal, g_salpha);

    // 1. prep small matrices
    prep_M_kernel<<<(WD * 600 + 255) / 256, 256>>>(conv_w, v);
    prep_cvb_kernel<<<1, 256>>>(conv_b, v, vb);
    prep_Wc2_kernel<<<(900 * CH + 255) / 256, 256>>>(conv_w);

    // 2. Q = emb @ M : [32000,300] x [300,600]
    {
        dim3 grid((600 + 127) / 128, VOCAB / 128);
        sgemm_kernel<<<grid, 256>>>(emb, pM, pQ, VOCAB, 600, WD, nullptr, nullptr);
    }

    // 3. attention scores
    score_kernel<<<B_SZ / 8, 256>>>(tok, q);

    // 4. softmax stats over batch axis
    softmax_stats_kernel<<<NW, 1024>>>();

    // 5. build G and sum-alpha
    gbuild_kernel<<<B_SZ, 320>>>(tok, emb);

    // 6. e = G @ Wc2 + salpha * conv_b : [32768,900] x [900,400]
    {
        dim3 grid((CH + 127) / 128, B_SZ / 128);
        sgemm_kernel<<<grid, 256>>>(pG, pWc2, out, B_SZ, CH, 900, psal, conv_b);
    }
}

// round 3
// speedup vs baseline: 1.6889x; 1.3398x over previous
#include <cuda_runtime.h>
#include <math.h>
#include <stdint.h>

#define B_SZ   32768
#define NW     30
#define VOCAB  32000
#define WD     300
#define CH     400
#define AD     200

// ---------------- scratch (static device globals; no allocation) ----------------
__device__ float g_M[WD * 600];          // B-matrix for Q gemm: [i][k*200+a]
__device__ float g_cvb[AD];              // conv_b @ v + vb
__device__ float g_Q[VOCAB * 600];       // [tok][k*200+a]   (76.8 MB)
__device__ float g_aT[NW * B_SZ];        // scores transposed: [n][b]
__device__ float g_mx[NW];
__device__ float g_isum[NW];
__device__ float g_G[(size_t)B_SZ * 900];// [b][k*300+i]     (118 MB)
__device__ float g_salpha[B_SZ];
__device__ float g_Wc2[900 * CH];        // [k*300+i][o]

// ---------------- prep: M[i][k*200+a] = sum_o conv_w[o,i,k] * v[o,a] ----------------
__global__ void prep_M_kernel(const float* __restrict__ conv_w, const float* __restrict__ v)
{
    int idx = blockIdx.x * blockDim.x + threadIdx.x;
    if (idx >= WD * 600) return;
    int i = idx / 600;
    int r = idx % 600;
    int k = r / 200;
    int a = r % 200;
    float s = 0.f;
    #pragma unroll 4
    for (int o = 0; o < CH; o++)
        s += conv_w[o * (WD * 3) + i * 3 + k] * v[o * AD + a];
    g_M[idx] = s;
}

// cvb[a] = vb[a] + sum_o conv_b[o]*v[o,a]
__global__ void prep_cvb_kernel(const float* __restrict__ conv_b,
                                const float* __restrict__ v,
                                const float* __restrict__ vb)
{
    int a = blockIdx.x * blockDim.x + threadIdx.x;
    if (a >= AD) return;
    float s = vb[a];
    for (int o = 0; o < CH; o++) s += conv_b[o] * v[o * AD + a];
    g_cvb[a] = s;
}

// Wc2[k*300+i][o] = conv_w[o,i,k]
__global__ void prep_Wc2_kernel(const float* __restrict__ conv_w)
{
    int idx = blockIdx.x * blockDim.x + threadIdx.x;
    if (idx >= 900 * CH) return;
    int row = idx / CH;          // k*300 + i
    int o   = idx % CH;
    int k = row / WD;
    int i = row % WD;
    g_Wc2[idx] = conv_w[o * (WD * 3) + i * 3 + k];
}

// ---------------- tf32 tensor-core GEMM ----------------
// C[M,N] = A[M,K] @ B[K,N] (+ rs[m]*bias[n]), fp32 accumulate.
// 256 threads, block tile 128x128, BK=16, warp tile 64x32 (4x4 m16n8k8 tiles),
// double-buffered smem of pre-converted tf32 bits.
// M must be a multiple of 128; N,K arbitrary (guarded).

__device__ __forceinline__ uint32_t f2tf32(float x)
{
    uint32_t r;
    asm("cvt.rna.tf32.f32 %0, %1;" : "=r"(r) : "f"(x));
    return r;
}

__device__ __forceinline__ void mma_tf32(float* c,
                                         uint32_t a0, uint32_t a1, uint32_t a2, uint32_t a3,
                                         uint32_t b0, uint32_t b1)
{
    asm volatile(
        "mma.sync.aligned.m16n8k8.row.col.f32.tf32.tf32.f32 "
        "{%0,%1,%2,%3}, {%4,%5,%6,%7}, {%8,%9}, {%0,%1,%2,%3};\n"
        : "+f"(c[0]), "+f"(c[1]), "+f"(c[2]), "+f"(c[3])
        : "r"(a0), "r"(a1), "r"(a2), "r"(a3), "r"(b0), "r"(b1));
}

#define AS_STRIDE 20    // [m][k] rows of 16 tf32 + pad 4 -> conflict-free frag loads
#define BS_STRIDE 136   // [k][n] rows of 128 tf32 + pad 8 -> conflict-free frag loads

__global__ __launch_bounds__(256, 2)
void tgemm_kernel(const float* __restrict__ A, const float* __restrict__ B,
                  float* __restrict__ C, int M, int N, int K,
                  const float* __restrict__ rs, const float* __restrict__ bias)
{
    __shared__ uint32_t As[2][128][AS_STRIDE];
    __shared__ uint32_t Bs[2][16][BS_STRIDE];

    const int tid    = threadIdx.x;
    const int lane   = tid & 31;
    const int warp   = tid >> 5;
    const int warp_m = warp & 1;      // 2 warps along M
    const int warp_n = warp >> 1;     // 4 warps along N
    const int m0 = blockIdx.y * 128;
    const int n0 = blockIdx.x * 128;

    // A loader: 128x16 tile, each thread 2 float4 (rows am, am+64; cols ak..ak+3)
    const int am = tid >> 2;          // 0..63
    const int ak = (tid & 3) * 4;     // 0,4,8,12

    float acc[4][4][4];
    #pragma unroll
    for (int mt = 0; mt < 4; mt++)
        #pragma unroll
        for (int nt = 0; nt < 4; nt++)
            #pragma unroll
            for (int i = 0; i < 4; i++) acc[mt][nt][i] = 0.f;

    auto ldA = [&](int kk0, int r) -> float4 {
        const int m  = am + r * 64;
        const int kg = kk0 + ak;
        const float* p = A + (size_t)(m0 + m) * K + kg;
        float4 v;
        if (kg + 3 < K) {
            v = *reinterpret_cast<const float4*>(p);
        } else {
            v.x = (kg + 0 < K) ? p[0] : 0.f;
            v.y = (kg + 1 < K) ? p[1] : 0.f;
            v.z = (kg + 2 < K) ? p[2] : 0.f;
            v.w = (kg + 3 < K) ? p[3] : 0.f;
        }
        return v;
    };
    auto ldB = [&](int kk0, int r) -> float4 {
        const int idx = tid + r * 256;
        const int k   = idx >> 5;           // 0..15
        const int n4  = (idx & 31) * 4;     // 0..124
        const int kg  = kk0 + k;
        const int ng  = n0 + n4;
        float4 v = make_float4(0.f, 0.f, 0.f, 0.f);
        if (kg < K) {
            const float* p = B + (size_t)kg * N + ng;
            if (ng + 3 < N) {
                v = *reinterpret_cast<const float4*>(p);
            } else {
                if (ng + 0 < N) v.x = p[0];
                if (ng + 1 < N) v.y = p[1];
                if (ng + 2 < N) v.z = p[2];
                if (ng + 3 < N) v.w = p[3];
            }
        }
        return v;
    };
    auto stA = [&](int buf, int r, float4 v) {
        const int m = am + r * 64;
        uint32_t* p = &As[buf][m][ak];
        p[0] = f2tf32(v.x); p[1] = f2tf32(v.y); p[2] = f2tf32(v.z); p[3] = f2tf32(v.w);
    };
    auto stB = [&](int buf, int r, float4 v) {
        const int idx = tid + r * 256;
        const int k   = idx >> 5;
        const int n4  = (idx & 31) * 4;
        uint32_t* p = &Bs[buf][k][n4];
        p[0] = f2tf32(v.x); p[1] = f2tf32(v.y); p[2] = f2tf32(v.z); p[3] = f2tf32(v.w);
    };

    // ---- preload panel 0 ----
    {
        float4 a0v = ldA(0, 0), a1v = ldA(0, 1);
        float4 b0v = ldB(0, 0), b1v = ldB(0, 1);
        stA(0, 0, a0v); stA(0, 1, a1v);
        stB(0, 0, b0v); stB(0, 1, b1v);
    }
    __syncthreads();

    const int nIter = (K + 15) / 16;
    int buf = 0;

    for (int it = 0; it < nIter; ++it) {
        const bool hasNext = (it + 1 < nIter);
        float4 a0v, a1v, b0v, b1v;
        if (hasNext) {
            const int kk0 = (it + 1) * 16;
            a0v = ldA(kk0, 0); a1v = ldA(kk0, 1);
            b0v = ldB(kk0, 0); b1v = ldB(kk0, 1);
        }

        // ---- compute 2 x k8 on current buffer ----
        #pragma unroll
        for (int ks = 0; ks < 2; ks++) {
            const int kb = ks * 8;
            const int kc = kb + (lane & 3);
            uint32_t af[4][4], bf[4][2];
            #pragma unroll
            for (int mt = 0; mt < 4; mt++) {
                const int rb = warp_m * 64 + mt * 16 + (lane >> 2);
                af[mt][0] = As[buf][rb    ][kc];
                af[mt][1] = As[buf][rb + 8][kc];
                af[mt][2] = As[buf][rb    ][kc + 4];
                af[mt][3] = As[buf][rb + 8][kc + 4];
            }
            #pragma unroll
            for (int nt = 0; nt < 4; nt++) {
                const int nc = warp_n * 32 + nt * 8 + (lane >> 2);
                bf[nt][0] = Bs[buf][kc    ][nc];
                bf[nt][1] = Bs[buf][kc + 4][nc];
            }
            #pragma unroll
            for (int mt = 0; mt < 4; mt++)
                #pragma unroll
                for (int nt = 0; nt < 4; nt++)
                    mma_tf32(acc[mt][nt], af[mt][0], af[mt][1], af[mt][2], af[mt][3],
                             bf[nt][0], bf[nt][1]);
        }

        if (hasNext) {
            stA(buf ^ 1, 0, a0v); stA(buf ^ 1, 1, a1v);
            stB(buf ^ 1, 0, b0v); stB(buf ^ 1, 1, b1v);
        }
        __syncthreads();
        buf ^= 1;
    }

    // ---- epilogue: c0,c1 -> (row, col..col+1), c2,c3 -> (row+8, col..col+1) ----
    #pragma unroll
    for (int mt = 0; mt < 4; mt++) {
        const int row = m0 + warp_m * 64 + mt * 16 + (lane >> 2);
        const float r0 = rs ? rs[row]     : 0.f;
        const float r1 = rs ? rs[row + 8] : 0.f;
        #pragma unroll
        for (int nt = 0; nt < 4; nt++) {
            const int col = n0 + warp_n * 32 + nt * 8 + (lane & 3) * 2;
            if (col < N) {
                float v0 = acc[mt][nt][0];
                float v2 = acc[mt][nt][2];
                if (bias) { v0 += r0 * bias[col]; v2 += r1 * bias[col]; }
                C[(size_t)row * N + col]       = v0;
                C[(size_t)(row + 8) * N + col] = v2;
            }
            if (col + 1 < N) {
                float v1 = acc[mt][nt][1];
                float v3 = acc[mt][nt][3];
                if (bias) { v1 += r0 * bias[col + 1]; v3 += r1 * bias[col + 1]; }
                C[(size_t)row * N + col + 1]       = v1;
                C[(size_t)(row + 8) * N + col + 1] = v3;
            }
        }
    }
}

// ---------------- scores: a[b,n] = q . tanh(cvb + Q0[t_{n-1}] + Q1[t_n] + Q2[t_{n+1}]) ----------------
// one warp per b; 8 warps per block; float4 gathers
__global__ __launch_bounds__(256)
void score_kernel(const int* __restrict__ tok, const float* __restrict__ qv)
{
    __shared__ float4 sq[AD / 4];       // 50
    __shared__ float4 scvb[AD / 4];     // 50
    __shared__ int stok[8][NW];

    const int tid = threadIdx.x;
    const int wid = tid >> 5;
    const int lane = tid & 31;
    const int b = blockIdx.x * 8 + wid;

    if (tid < AD / 4) {
        sq[tid]   = reinterpret_cast<const float4*>(qv)[tid];
        scvb[tid] = reinterpret_cast<const float4*>(g_cvb)[tid];
    }
    if (lane < NW) stok[wid][lane] = tok[b * NW + lane];
    __syncthreads();

    for (int n = 0; n < NW; n++) {
        const int tc  = stok[wid][n];
        const int tp  = (n > 0)      ? stok[wid][n - 1] : -1;
        const int tn2 = (n < NW - 1) ? stok[wid][n + 1] : -1;
        const float4* q1 = reinterpret_cast<const float4*>(g_Q + (size_t)tc * 600 + 200);
        const float4* q0 = (tp  >= 0) ? reinterpret_cast<const float4*>(g_Q + (size_t)tp  * 600)       : nullptr;
        const float4* q2 = (tn2 >= 0) ? reinterpret_cast<const float4*>(g_Q + (size_t)tn2 * 600 + 400) : nullptr;

        float s = 0.f;
        #pragma unroll
        for (int a4 = lane; a4 < AD / 4; a4 += 32) {
            float4 h = scvb[a4];
            float4 c = q1[a4];
            h.x += c.x; h.y += c.y; h.z += c.z; h.w += c.w;
            if (q0) { float4 p = q0[a4]; h.x += p.x; h.y += p.y; h.z += p.z; h.w += p.w; }
            if (q2) { float4 p = q2[a4]; h.x += p.x; h.y += p.y; h.z += p.z; h.w += p.w; }
            float4 qq = sq[a4];
            s += tanhf(h.x) * qq.x + tanhf(h.y) * qq.y + tanhf(h.z) * qq.z + tanhf(h.w) * qq.w;
        }
        #pragma unroll
        for (int off = 16; off; off >>= 1)
            s += __shfl_down_sync(0xffffffffu, s, off);
        if (lane == 0) g_aT[n * B_SZ + b] = s;
    }
}

// ---------------- softmax stats over batch axis, one block per n ----------------
__global__ __launch_bounds__(1024)
void softmax_stats_kernel()
{
    __shared__ float red[1024];
    const int n = blockIdx.x;
    const int tid = threadIdx.x;
    const float* row = g_aT + (size_t)n * B_SZ;

    float mx = -INFINITY;
    for (int b = tid; b < B_SZ; b += 1024) mx = fmaxf(mx, row[b]);
    red[tid] = mx;
    __syncthreads();
    for (int s = 512; s > 0; s >>= 1) {
        if (tid < s) red[tid] = fmaxf(red[tid], red[tid + s]);
        __syncthreads();
    }
    mx = red[0];
    __syncthreads();

    float sum = 0.f;
    for (int b = tid; b < B_SZ; b += 1024) sum += expf(row[b] - mx);
    red[tid] = sum;
    __syncthreads();
    for (int s = 512; s > 0; s >>= 1) {
        if (tid < s) red[tid] += red[tid + s];
        __syncthreads();
    }
    if (tid == 0) { g_mx[n] = mx; g_isum[n] = 1.f / red[0]; }
}

// ---------------- build G[b,k,i] = sum_n alpha[b,n] * E[b,n+k-1,i] ----------------
// one block per b, 320 threads (i = 0..299 active for the weighted sums)
__global__ __launch_bounds__(320)
void gbuild_kernel(const int* __restrict__ tok, const float* __restrict__ emb)
{
    __shared__ float sal[NW];
    __shared__ int stok[NW];
    const int b = blockIdx.x;
    const int tid = threadIdx.x;

    if (tid < NW) {
        sal[tid] = expf(g_aT[tid * B_SZ + b] - g_mx[tid]) * g_isum[tid];
        stok[tid] = tok[b * NW + tid];
    }
    __syncthreads();

    if (tid == 0) {
        float s = 0.f;
        #pragma unroll
        for (int n = 0; n < NW; n++) s += sal[n];
        g_salpha[b] = s;
    }

    const int i = tid;
    if (i < WD) {
        float g0 = 0.f, g1 = 0.f, g2 = 0.f;
        #pragma unroll 5
        for (int m = 0; m < NW; m++) {
            const float em = emb[(size_t)stok[m] * WD + i];
            g1 += sal[m] * em;
            if (m < NW - 1) g0 += sal[m + 1] * em;
            if (m > 0)      g2 += sal[m - 1] * em;
        }
        float* gp = g_G + (size_t)b * 900;
        gp[i]       = g0;
        gp[300 + i] = g1;
        gp[600 + i] = g2;
    }
}

// ---------------- launch ----------------
extern "C" void kernel_launch(void* const* d_in, const int* in_sizes, int n_in,
                              void* d_out, int out_size)
{
    const int*   tok    = (const int*)  d_in[0];   // [32768,30]
    const float* emb    = (const float*)d_in[1];   // [32000,300]
    const float* conv_w = (const float*)d_in[2];   // [400,300,3]
    const float* conv_b = (const float*)d_in[3];   // [400]
    const float* v      = (const float*)d_in[4];   // [400,200]
    const float* vb     = (const float*)d_in[5];   // [200]
    const float* q      = (const float*)d_in[6];   // [200,1]
    float* out = (float*)d_out;                    // [32768,400]

    float *pM, *pQ, *pG, *pWc2, *psal;
    cudaGetSymbolAddress((void**)&pM,   g_M);
    cudaGetSymbolAddress((void**)&pQ,   g_Q);
    cudaGetSymbolAddress((void**)&pG,   g_G);
    cudaGetSymbolAddress((void**)&pWc2, g_Wc2);
    cudaGetSymbolAddress((void**)&psal, g_salpha);

    // 1. prep small matrices
    prep_M_kernel<<<(WD * 600 + 255) / 256, 256>>>(conv_w, v);
    prep_cvb_kernel<<<1, 256>>>(conv_b, v, vb);
    prep_Wc2_kernel<<<(900 * CH + 255) / 256, 256>>>(conv_w);

    // 2. Q = emb @ M : [32000,300] x [300,600]  (tf32 tensor cores)
    {
        dim3 grid((600 + 127) / 128, VOCAB / 128);
        tgemm_kernel<<<grid, 256>>>(emb, pM, pQ, VOCAB, 600, WD, nullptr, nullptr);
    }

    // 3. attention scores
    score_kernel<<<B_SZ / 8, 256>>>(tok, q);

    // 4. softmax stats over batch axis
    softmax_stats_kernel<<<NW, 1024>>>();

    // 5. build G and sum-alpha
    gbuild_kernel<<<B_SZ, 320>>>(tok, emb);

    // 6. e = G @ Wc2 + salpha * conv_b : [32768,900] x [900,400]  (tf32 tensor cores)
    {
        dim3 grid((CH + 127) / 128, B_SZ / 128);
        tgemm_kernel<<<grid, 256>>>(pG, pWc2, out, B_SZ, CH, 900, psal, conv_b);
    }
}

// round 4
// speedup vs baseline: 2.4698x; 1.4624x over previous
#include <cuda_runtime.h>
#include <math.h>
#include <stdint.h>

#define B_SZ   32768
#define NW     30
#define VOCAB  32000
#define WD     300
#define CH     400
#define AD     200

// ---------------- scratch (static device globals; no allocation) ----------------
__device__ float g_M[WD * 600];          // B-matrix for Q gemm: [i][k*200+a]
__device__ float g_cvb[AD];              // conv_b @ v + vb
__device__ float g_Q[VOCAB * 600];       // [tok][k*200+a]   (76.8 MB)
__device__ float g_aT[NW * B_SZ];        // scores transposed: [n][b]
__device__ float g_mx[NW];
__device__ float g_isum[NW];
__device__ float g_G[(size_t)B_SZ * 900];// [b][k*300+i]     (118 MB)
__device__ float g_salpha[B_SZ];
__device__ float g_Wc2[900 * CH];        // [k*300+i][o]

// ---------------- prep kernels ----------------
__global__ void prep_M_kernel(const float* __restrict__ conv_w, const float* __restrict__ v)
{
    int idx = blockIdx.x * blockDim.x + threadIdx.x;
    if (idx >= WD * 600) return;
    int i = idx / 600;
    int r = idx % 600;
    int k = r / 200;
    int a = r % 200;
    float s = 0.f;
    #pragma unroll 4
    for (int o = 0; o < CH; o++)
        s += conv_w[o * (WD * 3) + i * 3 + k] * v[o * AD + a];
    g_M[idx] = s;
}

__global__ void prep_cvb_kernel(const float* __restrict__ conv_b,
                                const float* __restrict__ v,
                                const float* __restrict__ vb)
{
    int a = blockIdx.x * blockDim.x + threadIdx.x;
    if (a >= AD) return;
    float s = vb[a];
    for (int o = 0; o < CH; o++) s += conv_b[o] * v[o * AD + a];
    g_cvb[a] = s;
}

__global__ void prep_Wc2_kernel(const float* __restrict__ conv_w)
{
    int idx = blockIdx.x * blockDim.x + threadIdx.x;
    if (idx >= 900 * CH) return;
    int row = idx / CH;          // k*300 + i
    int o   = idx % CH;
    int k = row / WD;
    int i = row % WD;
    g_Wc2[idx] = conv_w[o * (WD * 3) + i * 3 + k];
}

// ---------------- tf32 tensor-core GEMM v2 ----------------
// C[M,N] = A[M,K] @ B[K,N] (+ rs[m]*bias[n]), fp32 accumulate.
// Block tile 128x128, BK=16, 128 threads (4 warps, 2x2), warp tile 64x64
// (4x8 m16n8k8 tiles). Double-buffered smem, k-paired A layout for LDS.64.
// M must be a multiple of 128.

__device__ __forceinline__ uint32_t f2tf32(float x)
{
    uint32_t r;
    asm("cvt.rna.tf32.f32 %0, %1;" : "=r"(r) : "f"(x));
    return r;
}

__device__ __forceinline__ void mma_tf32(float* c,
                                         uint32_t a0, uint32_t a1, uint32_t a2, uint32_t a3,
                                         uint32_t b0, uint32_t b1)
{
    asm volatile(
        "mma.sync.aligned.m16n8k8.row.col.f32.tf32.tf32.f32 "
        "{%0,%1,%2,%3}, {%4,%5,%6,%7}, {%8,%9}, {%0,%1,%2,%3};\n"
        : "+f"(c[0]), "+f"(c[1]), "+f"(c[2]), "+f"(c[3])
        : "r"(a0), "r"(a1), "r"(a2), "r"(a3), "r"(b0), "r"(b1));
}

#define AS_W 18    // 16 k-entries (paired layout) + 2 pad words
#define BS_W 136   // 128 n + 8 pad

__global__ __launch_bounds__(128, 2)
void tgemm_kernel(const float* __restrict__ A, const float* __restrict__ B,
                  float* __restrict__ C, int M, int N, int K,
                  const float* __restrict__ rs, const float* __restrict__ bias)
{
    // A paired layout: As[m][pos], pos(k) = (k>=8?8:0) + (k&3)*2 + ((k>>2)&1)
    __shared__ uint32_t As[2][128][AS_W];
    __shared__ uint32_t Bs[2][16][BS_W];

    const int tid    = threadIdx.x;
    const int lane   = tid & 31;
    const int warp   = tid >> 5;
    const int warp_m = warp & 1;      // 2 warps along M
    const int warp_n = warp >> 1;     // 2 warps along N
    const int m0 = blockIdx.y * 128;
    const int n0 = blockIdx.x * 128;

    // A loader: rows (tid>>2) + r*32, k-cols (tid&3)*4 .. +3
    const int am = tid >> 2;          // 0..31
    const int ak = (tid & 3) * 4;     // 0,4,8,12

    float acc[4][8][4];
    #pragma unroll
    for (int mt = 0; mt < 4; mt++)
        #pragma unroll
        for (int nt = 0; nt < 8; nt++)
            #pragma unroll
            for (int i = 0; i < 4; i++) acc[mt][nt][i] = 0.f;

    auto ldA = [&](int kk0, int r) -> float4 {
        const int m  = am + r * 32;
        const int kg = kk0 + ak;
        const float* p = A + (size_t)(m0 + m) * K + kg;
        float4 v;
        if (kg + 3 < K) {
            v = *reinterpret_cast<const float4*>(p);
        } else {
            v.x = (kg + 0 < K) ? p[0] : 0.f;
            v.y = (kg + 1 < K) ? p[1] : 0.f;
            v.z = (kg + 2 < K) ? p[2] : 0.f;
            v.w = (kg + 3 < K) ? p[3] : 0.f;
        }
        return v;
    };
    auto ldB = [&](int kk0, int r) -> float4 {
        const int idx = tid + r * 128;      // 0..511
        const int k   = idx >> 5;           // 0..15
        const int n4  = (idx & 31) * 4;     // 0..124
        const int kg  = kk0 + k;
        const int ng  = n0 + n4;
        float4 v = make_float4(0.f, 0.f, 0.f, 0.f);
        if (kg < K) {
            const float* p = B + (size_t)kg * N + ng;
            if (ng + 3 < N) {
                v = *reinterpret_cast<const float4*>(p);
            } else {
                if (ng + 0 < N) v.x = p[0];
                if (ng + 1 < N) v.y = p[1];
                if (ng + 2 < N) v.z = p[2];
                if (ng + 3 < N) v.w = p[3];
            }
        }
        return v;
    };
    // paired A store: element j of the float4 is k = ak + j
    // pos = (ak>=8 ? 8 : 0) + j*2 + ((ak&4) ? 1 : 0)
    auto stA = [&](int buf, int r, float4 v) {
        const int m = am + r * 32;
        const int base = ((ak & 8) ? 8 : 0) + ((ak & 4) ? 1 : 0);
        uint32_t* p = &As[buf][m][base];
        p[0] = f2tf32(v.x);
        p[2] = f2tf32(v.y);
        p[4] = f2tf32(v.z);
        p[6] = f2tf32(v.w);
    };
    auto stB = [&](int buf, int r, float4 v) {
        const int idx = tid + r * 128;
        const int k   = idx >> 5;
        const int n4  = (idx & 31) * 4;
        uint32_t* p = &Bs[buf][k][n4];
        uint4 w;
        w.x = f2tf32(v.x); w.y = f2tf32(v.y); w.z = f2tf32(v.z); w.w = f2tf32(v.w);
        *reinterpret_cast<uint4*>(p) = w;
    };

    // ---- preload panel 0 ----
    {
        float4 a0v = ldA(0, 0), a1v = ldA(0, 1), a2v = ldA(0, 2), a3v = ldA(0, 3);
        float4 b0v = ldB(0, 0), b1v = ldB(0, 1), b2v = ldB(0, 2), b3v = ldB(0, 3);
        stA(0, 0, a0v); stA(0, 1, a1v); stA(0, 2, a2v); stA(0, 3, a3v);
        stB(0, 0, b0v); stB(0, 1, b1v); stB(0, 2, b2v); stB(0, 3, b3v);
    }
    __syncthreads();

    const int nIter = (K + 15) / 16;
    int buf = 0;

    for (int it = 0; it < nIter; ++it) {
        const bool hasNext = (it + 1 < nIter);
        float4 a0v, a1v, a2v, a3v, b0v, b1v, b2v, b3v;
        if (hasNext) {
            const int kk0 = (it + 1) * 16;
            a0v = ldA(kk0, 0); a1v = ldA(kk0, 1); a2v = ldA(kk0, 2); a3v = ldA(kk0, 3);
            b0v = ldB(kk0, 0); b1v = ldB(kk0, 1); b2v = ldB(kk0, 2); b3v = ldB(kk0, 3);
        }

        // ---- compute 2 x k8 on current buffer ----
        #pragma unroll
        for (int ks = 0; ks < 2; ks++) {
            const int kc  = lane & 3;
            const int kof = ks * 8 + kc * 2;     // word offset of (k, k+4) pair
            uint32_t af[4][4];
            uint32_t bf[8][2];
            #pragma unroll
            for (int mt = 0; mt < 4; mt++) {
                const int rb = warp_m * 64 + mt * 16 + (lane >> 2);
                uint2 lo = *reinterpret_cast<const uint2*>(&As[buf][rb    ][kof]);
                uint2 hi = *reinterpret_cast<const uint2*>(&As[buf][rb + 8][kof]);
                af[mt][0] = lo.x;   // (row,   k)
                af[mt][1] = hi.x;   // (row+8, k)
                af[mt][2] = lo.y;   // (row,   k+4)
                af[mt][3] = hi.y;   // (row+8, k+4)
            }
            const int kb = ks * 8 + kc;
            #pragma unroll
            for (int nt = 0; nt < 8; nt++) {
                const int nc = warp_n * 64 + nt * 8 + (lane >> 2);
                bf[nt][0] = Bs[buf][kb    ][nc];
                bf[nt][1] = Bs[buf][kb + 4][nc];
            }
            #pragma unroll
            for (int mt = 0; mt < 4; mt++)
                #pragma unroll
                for (int nt = 0; nt < 8; nt++)
                    mma_tf32(acc[mt][nt], af[mt][0], af[mt][1], af[mt][2], af[mt][3],
                             bf[nt][0], bf[nt][1]);
        }

        if (hasNext) {
            stA(buf ^ 1, 0, a0v); stA(buf ^ 1, 1, a1v); stA(buf ^ 1, 2, a2v); stA(buf ^ 1, 3, a3v);
            stB(buf ^ 1, 0, b0v); stB(buf ^ 1, 1, b1v); stB(buf ^ 1, 2, b2v); stB(buf ^ 1, 3, b3v);
        }
        __syncthreads();
        buf ^= 1;
    }

    // ---- epilogue (N assumed even; col pairs are even-aligned) ----
    #pragma unroll
    for (int mt = 0; mt < 4; mt++) {
        const int row0 = m0 + warp_m * 64 + mt * 16 + (lane >> 2);
        const int row1 = row0 + 8;
        const float r0 = rs ? rs[row0] : 0.f;
        const float r1 = rs ? rs[row1] : 0.f;
        #pragma unroll
        for (int nt = 0; nt < 8; nt++) {
            const int col = n0 + warp_n * 64 + nt * 8 + (lane & 3) * 2;
            if (col < N) {
                float v0 = acc[mt][nt][0], v1 = acc[mt][nt][1];
                float v2 = acc[mt][nt][2], v3 = acc[mt][nt][3];
                if (bias) {
                    const float b0 = bias[col], b1 = bias[col + 1];
                    v0 += r0 * b0; v1 += r0 * b1;
                    v2 += r1 * b0; v3 += r1 * b1;
                }
                *reinterpret_cast<float2*>(C + (size_t)row0 * N + col) = make_float2(v0, v1);
                *reinterpret_cast<float2*>(C + (size_t)row1 * N + col) = make_float2(v2, v3);
            }
        }
    }
}

// ---------------- scores: a[b,n] = q . tanh(cvb + Q0[t_{n-1}] + Q1[t_n] + Q2[t_{n+1}]) ----------------
__global__ __launch_bounds__(256)
void score_kernel(const int* __restrict__ tok, const float* __restrict__ qv)
{
    __shared__ float4 sq[AD / 4];       // 50
    __shared__ float4 scvb[AD / 4];     // 50
    __shared__ int stok[8][NW];

    const int tid = threadIdx.x;
    const int wid = tid >> 5;
    const int lane = tid & 31;
    const int b = blockIdx.x * 8 + wid;

    if (tid < AD / 4) {
        sq[tid]   = reinterpret_cast<const float4*>(qv)[tid];
        scvb[tid] = reinterpret_cast<const float4*>(g_cvb)[tid];
    }
    if (lane < NW) stok[wid][lane] = tok[b * NW + lane];
    __syncthreads();

    for (int n = 0; n < NW; n++) {
        const int tc  = stok[wid][n];
        const int tp  = (n > 0)      ? stok[wid][n - 1] : -1;
        const int tn2 = (n < NW - 1) ? stok[wid][n + 1] : -1;
        const float4* q1 = reinterpret_cast<const float4*>(g_Q + (size_t)tc * 600 + 200);
        const float4* q0 = (tp  >= 0) ? reinterpret_cast<const float4*>(g_Q + (size_t)tp  * 600)       : nullptr;
        const float4* q2 = (tn2 >= 0) ? reinterpret_cast<const float4*>(g_Q + (size_t)tn2 * 600 + 400) : nullptr;

        float s = 0.f;
        #pragma unroll
        for (int a4 = lane; a4 < AD / 4; a4 += 32) {
            float4 h = scvb[a4];
            float4 c = q1[a4];
            h.x += c.x; h.y += c.y; h.z += c.z; h.w += c.w;
            if (q0) { float4 p = q0[a4]; h.x += p.x; h.y += p.y; h.z += p.z; h.w += p.w; }
            if (q2) { float4 p = q2[a4]; h.x += p.x; h.y += p.y; h.z += p.z; h.w += p.w; }
            float4 qq = sq[a4];
            s += tanhf(h.x) * qq.x + tanhf(h.y) * qq.y + tanhf(h.z) * qq.z + tanhf(h.w) * qq.w;
        }
        #pragma unroll
        for (int off = 16; off; off >>= 1)
            s += __shfl_down_sync(0xffffffffu, s, off);
        if (lane == 0) g_aT[n * B_SZ + b] = s;
    }
}

// ---------------- softmax stats over batch axis, one block per n ----------------
__global__ __launch_bounds__(1024)
void softmax_stats_kernel()
{
    __shared__ float red[1024];
    const int n = blockIdx.x;
    const int tid = threadIdx.x;
    const float* row = g_aT + (size_t)n * B_SZ;

    float mx = -INFINITY;
    for (int b = tid; b < B_SZ; b += 1024) mx = fmaxf(mx, row[b]);
    red[tid] = mx;
    __syncthreads();
    for (int s = 512; s > 0; s >>= 1) {
        if (tid < s) red[tid] = fmaxf(red[tid], red[tid + s]);
        __syncthreads();
    }
    mx = red[0];
    __syncthreads();

    float sum = 0.f;
    for (int b = tid; b < B_SZ; b += 1024) sum += expf(row[b] - mx);
    red[tid] = sum;
    __syncthreads();
    for (int s = 512; s > 0; s >>= 1) {
        if (tid < s) red[tid] += red[tid + s];
        __syncthreads();
    }
    if (tid == 0) { g_mx[n] = mx; g_isum[n] = 1.f / red[0]; }
}

// ---------------- build G[b,k,i] = sum_n alpha[b,n] * E[b,n+k-1,i] ----------------
__global__ __launch_bounds__(320)
void gbuild_kernel(const int* __restrict__ tok, const float* __restrict__ emb)
{
    __shared__ float sal[NW];
    __shared__ int stok[NW];
    const int b = blockIdx.x;
    const int tid = threadIdx.x;

    if (tid < NW) {
        sal[tid] = expf(g_aT[tid * B_SZ + b] - g_mx[tid]) * g_isum[tid];
        stok[tid] = tok[b * NW + tid];
    }
    __syncthreads();

    if (tid == 0) {
        float s = 0.f;
        #pragma unroll
        for (int n = 0; n < NW; n++) s += sal[n];
        g_salpha[b] = s;
    }

    const int i = tid;
    if (i < WD) {
        float g0 = 0.f, g1 = 0.f, g2 = 0.f;
        #pragma unroll 5
        for (int m = 0; m < NW; m++) {
            const float em = emb[(size_t)stok[m] * WD + i];
            g1 += sal[m] * em;
            if (m < NW - 1) g0 += sal[m + 1] * em;
            if (m > 0)      g2 += sal[m - 1] * em;
        }
        float* gp = g_G + (size_t)b * 900;
        gp[i]       = g0;
        gp[300 + i] = g1;
        gp[600 + i] = g2;
    }
}

// ---------------- launch ----------------
extern "C" void kernel_launch(void* const* d_in, const int* in_sizes, int n_in,
                              void* d_out, int out_size)
{
    const int*   tok    = (const int*)  d_in[0];   // [32768,30]
    const float* emb    = (const float*)d_in[1];   // [32000,300]
    const float* conv_w = (const float*)d_in[2];   // [400,300,3]
    const float* conv_b = (const float*)d_in[3];   // [400]
    const float* v      = (const float*)d_in[4];   // [400,200]
    const float* vb     = (const float*)d_in[5];   // [200]
    const float* q      = (const float*)d_in[6];   // [200,1]
    float* out = (float*)d_out;                    // [32768,400]

    float *pM, *pQ, *pG, *pWc2, *psal;
    cudaGetSymbolAddress((void**)&pM,   g_M);
    cudaGetSymbolAddress((void**)&pQ,   g_Q);
    cudaGetSymbolAddress((void**)&pG,   g_G);
    cudaGetSymbolAddress((void**)&pWc2, g_Wc2);
    cudaGetSymbolAddress((void**)&psal, g_salpha);

    // 1. prep small matrices
    prep_M_kernel<<<(WD * 600 + 255) / 256, 256>>>(conv_w, v);
    prep_cvb_kernel<<<1, 256>>>(conv_b, v, vb);
    prep_Wc2_kernel<<<(900 * CH + 255) / 256, 256>>>(conv_w);

    // 2. Q = emb @ M : [32000,300] x [300,600]  (tf32 tensor cores)
    {
        dim3 grid((600 + 127) / 128, VOCAB / 128);
        tgemm_kernel<<<grid, 128>>>(emb, pM, pQ, VOCAB, 600, WD, nullptr, nullptr);
    }

    // 3. attention scores
    score_kernel<<<B_SZ / 8, 256>>>(tok, q);

    // 4. softmax stats over batch axis
    softmax_stats_kernel<<<NW, 1024>>>();

    // 5. build G and sum-alpha
    gbuild_kernel<<<B_SZ, 320>>>(tok, emb);

    // 6. e = G @ Wc2 + salpha * conv_b : [32768,900] x [900,400]  (tf32 tensor cores)
    {
        dim3 grid((CH + 127) / 128, B_SZ / 128);
        tgemm_kernel<<<grid, 128>>>(pG, pWc2, out, B_SZ, CH, 900, psal, conv_b);
    }
}

// round 5
// speedup vs baseline: 2.9595x; 1.1983x over previous
#include <cuda_runtime.h>
#include <math.h>
#include <stdint.h>

#define B_SZ   32768
#define NW     30
#define VOCAB  32000
#define WD     300
#define CH     400
#define AD     200

// ---------------- scratch (static device globals; no allocation) ----------------
__device__ float g_M[WD * 600];            // tf32-rounded B for Q gemm: [i][k*200+a]
__device__ float g_cvb[AD];                // conv_b @ v + vb
__device__ float g_Q[VOCAB * 600];         // [tok][k*200+a]   (76.8 MB)
__device__ float g_aT[NW * B_SZ];          // scores transposed: [n][b]
__device__ float g_mx[NW];
__device__ float g_isum[NW];
__device__ float g_G[(size_t)B_SZ * 900];  // tf32-rounded [b][k*300+i]  (118 MB)
__device__ float g_salpha[B_SZ];
__device__ float g_Wc2[900 * CH];          // tf32-rounded [k*300+i][o]
__device__ float g_embT[VOCAB * WD];       // tf32-rounded emb copy (38.4 MB)

__device__ __forceinline__ uint32_t f2tf32(float x)
{
    uint32_t r;
    asm("cvt.rna.tf32.f32 %0, %1;" : "=r"(r) : "f"(x));
    return r;
}
__device__ __forceinline__ float rtf32(float x) { return __uint_as_float(f2tf32(x)); }

// ---------------- prep kernels ----------------
__global__ void prep_M_kernel(const float* __restrict__ conv_w, const float* __restrict__ v)
{
    int idx = blockIdx.x * blockDim.x + threadIdx.x;
    if (idx >= WD * 600) return;
    int i = idx / 600;
    int r = idx % 600;
    int k = r / 200;
    int a = r % 200;
    float s = 0.f;
    #pragma unroll 4
    for (int o = 0; o < CH; o++)
        s += conv_w[o * (WD * 3) + i * 3 + k] * v[o * AD + a];
    g_M[idx] = rtf32(s);
}

__global__ void prep_cvb_kernel(const float* __restrict__ conv_b,
                                const float* __restrict__ v,
                                const float* __restrict__ vb)
{
    int a = blockIdx.x * blockDim.x + threadIdx.x;
    if (a >= AD) return;
    float s = vb[a];
    for (int o = 0; o < CH; o++) s += conv_b[o] * v[o * AD + a];
    g_cvb[a] = s;
}

__global__ void prep_Wc2_kernel(const float* __restrict__ conv_w)
{
    int idx = blockIdx.x * blockDim.x + threadIdx.x;
    if (idx >= 900 * CH) return;
    int row = idx / CH;          // k*300 + i
    int o   = idx % CH;
    int k = row / WD;
    int i = row % WD;
    g_Wc2[idx] = rtf32(conv_w[o * (WD * 3) + i * 3 + k]);
}

// tf32-rounded copy of emb (float4 stream)
__global__ void round_emb_kernel(const float* __restrict__ emb)
{
    int idx = blockIdx.x * blockDim.x + threadIdx.x;      // float4 index
    const int n4 = VOCAB * WD / 4;                        // 2,400,000
    if (idx >= n4) return;
    float4 v = reinterpret_cast<const float4*>(emb)[idx];
    v.x = rtf32(v.x); v.y = rtf32(v.y); v.z = rtf32(v.z); v.w = rtf32(v.w);
    reinterpret_cast<float4*>(g_embT)[idx] = v;
}

// ---------------- tf32 tensor-core GEMM v3 (cp.async 3-stage) ----------------
// C[M,N] = A[M,K] @ B[K,N] (+ rs[m]*bias[n]), fp32 accumulate.
// A and B must already be tf32-rounded bits. Block tile 128x128, BK=16,
// 128 threads (4 warps, 2x2), warp tile 64x64. M multiple of 128.

__device__ __forceinline__ void mma_tf32(float* c,
                                         uint32_t a0, uint32_t a1, uint32_t a2, uint32_t a3,
                                         uint32_t b0, uint32_t b1)
{
    asm volatile(
        "mma.sync.aligned.m16n8k8.row.col.f32.tf32.tf32.f32 "
        "{%0,%1,%2,%3}, {%4,%5,%6,%7}, {%8,%9}, {%0,%1,%2,%3};\n"
        : "+f"(c[0]), "+f"(c[1]), "+f"(c[2]), "+f"(c[3])
        : "r"(a0), "r"(a1), "r"(a2), "r"(a3), "r"(b0), "r"(b1));
}

__device__ __forceinline__ void cp16(uint32_t dst, const void* src, int bytes)
{
    asm volatile("cp.async.cg.shared.global [%0], [%1], 16, %2;\n"
                 :: "r"(dst), "l"(src), "r"(bytes));
}

#define STAGES 3
#define AS_W 20     // 16 k + 4 pad words (80B rows, 16B aligned)
#define BS_W 136    // 128 n + 8 pad words (544B rows, 16B aligned)
#define GEMM_SMEM_BYTES (STAGES * (128 * AS_W + 16 * BS_W) * 4)   // 56832

__global__ __launch_bounds__(128, 2)
void tgemm_kernel(const float* __restrict__ A, const float* __restrict__ B,
                  float* __restrict__ C, int M, int N, int K,
                  const float* __restrict__ rs, const float* __restrict__ bias)
{
    extern __shared__ __align__(16) uint32_t smem[];
    uint32_t* Asm = smem;                           // [STAGES][128][AS_W]
    uint32_t* Bsm = smem + STAGES * 128 * AS_W;     // [STAGES][16][BS_W]
    const uint32_t as_base = (uint32_t)__cvta_generic_to_shared(Asm);
    const uint32_t bs_base = (uint32_t)__cvta_generic_to_shared(Bsm);

    const int tid    = threadIdx.x;
    const int lane   = tid & 31;
    const int warp   = tid >> 5;
    const int warp_m = warp & 1;
    const int warp_n = warp >> 1;
    const int m0 = blockIdx.y * 128;
    const int n0 = blockIdx.x * 128;

    const int am = tid >> 2;          // 0..31
    const int ak = (tid & 3) * 4;     // 0,4,8,12

    const int nIter = (K + 15) / 16;

    float acc[4][8][4];
    #pragma unroll
    for (int mt = 0; mt < 4; mt++)
        #pragma unroll
        for (int nt = 0; nt < 8; nt++)
            #pragma unroll
            for (int i = 0; i < 4; i++) acc[mt][nt][i] = 0.f;

    auto issue_panel = [&](int p) {
        const int s   = p % STAGES;
        const int kk0 = p * 16;
        // A: 4 chunks of 16B
        #pragma unroll
        for (int r = 0; r < 4; r++) {
            const int m  = am + r * 32;
            const int kg = kk0 + ak;
            int bytes = (K - kg) * 4;
            bytes = bytes < 0 ? 0 : (bytes > 16 ? 16 : bytes);
            const int kcl = kg < K ? kg : 0;
            const float* src = A + (size_t)(m0 + m) * K + kcl;
            const uint32_t dst = as_base + (((s * 128 + m) * AS_W) + ak) * 4;
            cp16(dst, src, bytes);
        }
        // B: 4 chunks of 16B
        #pragma unroll
        for (int r = 0; r < 4; r++) {
            const int idx = tid + r * 128;
            const int k   = idx >> 5;
            const int n4  = (idx & 31) * 4;
            const int kg  = kk0 + k;
            const int ng  = n0 + n4;
            int bytes = 0;
            const float* src = B;
            if (kg < K) {
                bytes = (N - ng) * 4;
                bytes = bytes < 0 ? 0 : (bytes > 16 ? 16 : bytes);
                src = B + (size_t)kg * N + (ng < N ? ng : 0);
            }
            const uint32_t dst = bs_base + (((s * 16 + k) * BS_W) + n4) * 4;
            cp16(dst, src, bytes);
        }
        asm volatile("cp.async.commit_group;\n");
    };

    // prologue: stages 0..STAGES-2
    issue_panel(0);
    issue_panel(1);

    for (int it = 0; it < nIter; ++it) {
        asm volatile("cp.async.wait_group %0;\n" :: "n"(STAGES - 2));
        __syncthreads();

        const int s = it % STAGES;
        const uint32_t* Asb = Asm + s * 128 * AS_W;
        const uint32_t* Bsb = Bsm + s * 16 * BS_W;

        #pragma unroll
        for (int ks = 0; ks < 2; ks++) {
            const int kb = ks * 8 + (lane & 3);
            uint32_t af[4][4];
            uint32_t bf[8][2];
            #pragma unroll
            for (int mt = 0; mt < 4; mt++) {
                const int rb = warp_m * 64 + mt * 16 + (lane >> 2);
                af[mt][0] = Asb[rb * AS_W + kb];
                af[mt][1] = Asb[(rb + 8) * AS_W + kb];
                af[mt][2] = Asb[rb * AS_W + kb + 4];
                af[mt][3] = Asb[(rb + 8) * AS_W + kb + 4];
            }
            #pragma unroll
            for (int nt = 0; nt < 8; nt++) {
                const int nc = warp_n * 64 + nt * 8 + (lane >> 2);
                bf[nt][0] = Bsb[kb * BS_W + nc];
                bf[nt][1] = Bsb[(kb + 4) * BS_W + nc];
            }
            #pragma unroll
            for (int mt = 0; mt < 4; mt++)
                #pragma unroll
                for (int nt = 0; nt < 8; nt++)
                    mma_tf32(acc[mt][nt], af[mt][0], af[mt][1], af[mt][2], af[mt][3],
                             bf[nt][0], bf[nt][1]);
        }

        // issue panel it+STAGES-1 (its slot was consumed at iter it-1);
        // always commit so group counting stays uniform
        if (it + STAGES - 1 < nIter) {
            issue_panel(it + STAGES - 1);
        } else {
            asm volatile("cp.async.commit_group;\n");
        }
    }

    // ---- epilogue (N even; col pairs even-aligned) ----
    #pragma unroll
    for (int mt = 0; mt < 4; mt++) {
        const int row0 = m0 + warp_m * 64 + mt * 16 + (lane >> 2);
        const int row1 = row0 + 8;
        const float r0 = rs ? rs[row0] : 0.f;
        const float r1 = rs ? rs[row1] : 0.f;
        #pragma unroll
        for (int nt = 0; nt < 8; nt++) {
            const int col = n0 + warp_n * 64 + nt * 8 + (lane & 3) * 2;
            if (col < N) {
                float v0 = acc[mt][nt][0], v1 = acc[mt][nt][1];
                float v2 = acc[mt][nt][2], v3 = acc[mt][nt][3];
                if (bias) {
                    const float b0 = bias[col], b1 = bias[col + 1];
                    v0 += r0 * b0; v1 += r0 * b1;
                    v2 += r1 * b0; v3 += r1 * b1;
                }
                *reinterpret_cast<float2*>(C + (size_t)row0 * N + col) = make_float2(v0, v1);
                *reinterpret_cast<float2*>(C + (size_t)row1 * N + col) = make_float2(v2, v3);
            }
        }
    }
}

// ---------------- scores: a[b,n] = q . tanh(cvb + Q0[t_{n-1}] + Q1[t_n] + Q2[t_{n+1}]) ----------------
__global__ __launch_bounds__(256)
void score_kernel(const int* __restrict__ tok, const float* __restrict__ qv)
{
    __shared__ float4 sq[AD / 4];
    __shared__ float4 scvb[AD / 4];
    __shared__ int stok[8][NW];

    const int tid = threadIdx.x;
    const int wid = tid >> 5;
    const int lane = tid & 31;
    const int b = blockIdx.x * 8 + wid;

    if (tid < AD / 4) {
        sq[tid]   = reinterpret_cast<const float4*>(qv)[tid];
        scvb[tid] = reinterpret_cast<const float4*>(g_cvb)[tid];
    }
    if (lane < NW) stok[wid][lane] = tok[b * NW + lane];
    __syncthreads();

    for (int n = 0; n < NW; n++) {
        const int tc  = stok[wid][n];
        const int tp  = (n > 0)      ? stok[wid][n - 1] : -1;
        const int tn2 = (n < NW - 1) ? stok[wid][n + 1] : -1;
        const float4* q1 = reinterpret_cast<const float4*>(g_Q + (size_t)tc * 600 + 200);
        const float4* q0 = (tp  >= 0) ? reinterpret_cast<const float4*>(g_Q + (size_t)tp  * 600)       : nullptr;
        const float4* q2 = (tn2 >= 0) ? reinterpret_cast<const float4*>(g_Q + (size_t)tn2 * 600 + 400) : nullptr;

        float s = 0.f;
        #pragma unroll
        for (int a4 = lane; a4 < AD / 4; a4 += 32) {
            float4 h = scvb[a4];
            float4 c = q1[a4];
            h.x += c.x; h.y += c.y; h.z += c.z; h.w += c.w;
            if (q0) { float4 p = q0[a4]; h.x += p.x; h.y += p.y; h.z += p.z; h.w += p.w; }
            if (q2) { float4 p = q2[a4]; h.x += p.x; h.y += p.y; h.z += p.z; h.w += p.w; }
            float4 qq = sq[a4];
            s += tanhf(h.x) * qq.x + tanhf(h.y) * qq.y + tanhf(h.z) * qq.z + tanhf(h.w) * qq.w;
        }
        #pragma unroll
        for (int off = 16; off; off >>= 1)
            s += __shfl_down_sync(0xffffffffu, s, off);
        if (lane == 0) g_aT[n * B_SZ + b] = s;
    }
}

// ---------------- softmax stats over batch axis, one block per n ----------------
__global__ __launch_bounds__(1024)
void softmax_stats_kernel()
{
    __shared__ float red[1024];
    const int n = blockIdx.x;
    const int tid = threadIdx.x;
    const float* row = g_aT + (size_t)n * B_SZ;

    float mx = -INFINITY;
    for (int b = tid; b < B_SZ; b += 1024) mx = fmaxf(mx, row[b]);
    red[tid] = mx;
    __syncthreads();
    for (int s = 512; s > 0; s >>= 1) {
        if (tid < s) red[tid] = fmaxf(red[tid], red[tid + s]);
        __syncthreads();
    }
    mx = red[0];
    __syncthreads();

    float sum = 0.f;
    for (int b = tid; b < B_SZ; b += 1024) sum += expf(row[b] - mx);
    red[tid] = sum;
    __syncthreads();
    for (int s = 512; s > 0; s >>= 1) {
        if (tid < s) red[tid] += red[tid + s];
        __syncthreads();
    }
    if (tid == 0) { g_mx[n] = mx; g_isum[n] = 1.f / red[0]; }
}

// ---------------- build G[b,k,i] = sum_n alpha[b,n] * E[b,n+k-1,i] (tf32-rounded) ----------
__global__ __launch_bounds__(320)
void gbuild_kernel(const int* __restrict__ tok, const float* __restrict__ emb)
{
    __shared__ float sal[NW];
    __shared__ int stok[NW];
    const int b = blockIdx.x;
    const int tid = threadIdx.x;

    if (tid < NW) {
        sal[tid] = expf(g_aT[tid * B_SZ + b] - g_mx[tid]) * g_isum[tid];
        stok[tid] = tok[b * NW + tid];
    }
    __syncthreads();

    if (tid == 0) {
        float s = 0.f;
        #pragma unroll
        for (int n = 0; n < NW; n++) s += sal[n];
        g_salpha[b] = s;
    }

    const int i = tid;
    if (i < WD) {
        float g0 = 0.f, g1 = 0.f, g2 = 0.f;
        #pragma unroll 5
        for (int m = 0; m < NW; m++) {
            const float em = emb[(size_t)stok[m] * WD + i];
            g1 += sal[m] * em;
            if (m < NW - 1) g0 += sal[m + 1] * em;
            if (m > 0)      g2 += sal[m - 1] * em;
        }
        float* gp = g_G + (size_t)b * 900;
        gp[i]       = rtf32(g0);
        gp[300 + i] = rtf32(g1);
        gp[600 + i] = rtf32(g2);
    }
}

// ---------------- launch ----------------
extern "C" void kernel_launch(void* const* d_in, const int* in_sizes, int n_in,
                              void* d_out, int out_size)
{
    const int*   tok    = (const int*)  d_in[0];   // [32768,30]
    const float* emb    = (const float*)d_in[1];   // [32000,300]
    const float* conv_w = (const float*)d_in[2];   // [400,300,3]
    const float* conv_b = (const float*)d_in[3];   // [400]
    const float* v      = (const float*)d_in[4];   // [400,200]
    const float* vb     = (const float*)d_in[5];   // [200]
    const float* q      = (const float*)d_in[6];   // [200,1]
    float* out = (float*)d_out;                    // [32768,400]

    float *pM, *pQ, *pG, *pWc2, *psal, *pembT;
    cudaGetSymbolAddress((void**)&pM,    g_M);
    cudaGetSymbolAddress((void**)&pQ,    g_Q);
    cudaGetSymbolAddress((void**)&pG,    g_G);
    cudaGetSymbolAddress((void**)&pWc2,  g_Wc2);
    cudaGetSymbolAddress((void**)&psal,  g_salpha);
    cudaGetSymbolAddress((void**)&pembT, g_embT);

    cudaFuncSetAttribute(tgemm_kernel,
                         cudaFuncAttributeMaxDynamicSharedMemorySize, GEMM_SMEM_BYTES);

    // 1. prep small matrices + tf32-rounded emb copy
    prep_M_kernel<<<(WD * 600 + 255) / 256, 256>>>(conv_w, v);
    prep_cvb_kernel<<<1, 256>>>(conv_b, v, vb);
    prep_Wc2_kernel<<<(900 * CH + 255) / 256, 256>>>(conv_w);
    round_emb_kernel<<<(VOCAB * WD / 4 + 255) / 256, 256>>>(emb);

    // 2. Q = embT @ M : [32000,300] x [300,600]  (tf32 tensor cores)
    {
        dim3 grid((600 + 127) / 128, VOCAB / 128);
        tgemm_kernel<<<grid, 128, GEMM_SMEM_BYTES>>>(pembT, pM, pQ, VOCAB, 600, WD,
                                                     nullptr, nullptr);
    }

    // 3. attention scores
    score_kernel<<<B_SZ / 8, 256>>>(tok, q);

    // 4. softmax stats over batch axis
    softmax_stats_kernel<<<NW, 1024>>>();

    // 5. build G (tf32-rounded) and sum-alpha
    gbuild_kernel<<<B_SZ, 320>>>(tok, emb);

    // 6. e = G @ Wc2 + salpha * conv_b : [32768,900] x [900,400]  (tf32 tensor cores)
    {
        dim3 grid((CH + 127) / 128, B_SZ / 128);
        tgemm_kernel<<<grid, 128, GEMM_SMEM_BYTES>>>(pG, pWc2, out, B_SZ, CH, 900,
                                                     psal, conv_b);
    }
}

// round 6
// speedup vs baseline: 3.5358x; 1.1947x over previous
#include <cuda_runtime.h>
#include <math.h>
#include <stdint.h>

#define B_SZ   32768
#define NW     30
#define VOCAB  32000
#define WD     300
#define CH     400
#define AD     200

// ---------------- scratch (static device globals; no allocation) ----------------
__device__ float g_M[WD * 600];            // tf32-rounded B for Q gemm: [i][k*200+a]
__device__ float g_cvb[AD];                // conv_b @ v + vb
__device__ float g_Q[VOCAB * 600];         // [tok][k*200+a]   (76.8 MB)
__device__ float g_aT[NW * B_SZ];          // scores transposed: [n][b]
__device__ float g_mx[NW];
__device__ float g_isum[NW];
__device__ float g_G[(size_t)B_SZ * 900];  // tf32-rounded [b][k*300+i]  (118 MB)
__device__ float g_salpha[B_SZ];
__device__ float g_Wc2[900 * CH];          // tf32-rounded [k*300+i][o]
__device__ float g_embT[VOCAB * WD];       // tf32-rounded emb copy (38.4 MB)

__device__ __forceinline__ uint32_t f2tf32(float x)
{
    uint32_t r;
    asm("cvt.rna.tf32.f32 %0, %1;" : "=r"(r) : "f"(x));
    return r;
}
__device__ __forceinline__ float rtf32(float x) { return __uint_as_float(f2tf32(x)); }

// fast tanh: 1 - 2/(exp(2x)+1); saturates correctly at +-inf
__device__ __forceinline__ float ftanh(float x)
{
    float e = __expf(2.f * x);
    return 1.f - __fdividef(2.f, e + 1.f);
}

// ---------------- prep kernels ----------------
__global__ void prep_M_kernel(const float* __restrict__ conv_w, const float* __restrict__ v)
{
    int idx = blockIdx.x * blockDim.x + threadIdx.x;
    if (idx >= WD * 600) return;
    int i = idx / 600;
    int r = idx % 600;
    int k = r / 200;
    int a = r % 200;
    float s = 0.f;
    #pragma unroll 4
    for (int o = 0; o < CH; o++)
        s += conv_w[o * (WD * 3) + i * 3 + k] * v[o * AD + a];
    g_M[idx] = rtf32(s);
}

__global__ void prep_cvb_kernel(const float* __restrict__ conv_b,
                                const float* __restrict__ v,
                                const float* __restrict__ vb)
{
    int a = blockIdx.x * blockDim.x + threadIdx.x;
    if (a >= AD) return;
    float s = vb[a];
    for (int o = 0; o < CH; o++) s += conv_b[o] * v[o * AD + a];
    g_cvb[a] = s;
}

__global__ void prep_Wc2_kernel(const float* __restrict__ conv_w)
{
    int idx = blockIdx.x * blockDim.x + threadIdx.x;
    if (idx >= 900 * CH) return;
    int row = idx / CH;          // k*300 + i
    int o   = idx % CH;
    int k = row / WD;
    int i = row % WD;
    g_Wc2[idx] = rtf32(conv_w[o * (WD * 3) + i * 3 + k]);
}

__global__ void round_emb_kernel(const float* __restrict__ emb)
{
    int idx = blockIdx.x * blockDim.x + threadIdx.x;      // float4 index
    const int n4 = VOCAB * WD / 4;
    if (idx >= n4) return;
    float4 v = reinterpret_cast<const float4*>(emb)[idx];
    v.x = rtf32(v.x); v.y = rtf32(v.y); v.z = rtf32(v.z); v.w = rtf32(v.w);
    reinterpret_cast<float4*>(g_embT)[idx] = v;
}

// ---------------- tf32 tensor-core GEMM v4 (cp.async 4-stage, templated BN) -----
// C[M,N] = A[M,K] @ B[K,N] (+ rs[m]*bias[n]), fp32 accumulate.
// A,B pre-rounded tf32 bits. Block tile 128 x BN, BK=16, 128 threads (4 warps,
// 2x2), warp tile 64 x BN/2. M multiple of 128.

__device__ __forceinline__ void mma_tf32(float* c,
                                         uint32_t a0, uint32_t a1, uint32_t a2, uint32_t a3,
                                         uint32_t b0, uint32_t b1)
{
    asm volatile(
        "mma.sync.aligned.m16n8k8.row.col.f32.tf32.tf32.f32 "
        "{%0,%1,%2,%3}, {%4,%5,%6,%7}, {%8,%9}, {%0,%1,%2,%3};\n"
        : "+f"(c[0]), "+f"(c[1]), "+f"(c[2]), "+f"(c[3])
        : "r"(a0), "r"(a1), "r"(a2), "r"(a3), "r"(b0), "r"(b1));
}

__device__ __forceinline__ void cp16(uint32_t dst, const void* src, int bytes)
{
    asm volatile("cp.async.cg.shared.global [%0], [%1], 16, %2;\n"
                 :: "r"(dst), "l"(src), "r"(bytes));
}

#define STAGES 4
#define AS_W 20     // 16 k + 4 pad words

template<int BN>
__global__ __launch_bounds__(128, (BN == 80) ? 3 : 2)
void tgemm_kernel(const float* __restrict__ A, const float* __restrict__ B,
                  float* __restrict__ C, int M, int N, int K,
                  const float* __restrict__ rs, const float* __restrict__ bias)
{
    constexpr int BS_W = BN + 8;
    constexpr int NT   = BN / 16;          // n8 tiles per warp
    constexpr int BCH  = 16 * BN / 4;      // float4 chunks per B panel
    constexpr int BRND = (BCH + 127) / 128;

    extern __shared__ __align__(16) uint32_t smem[];
    uint32_t* Asm = smem;                           // [STAGES][128][AS_W]
    uint32_t* Bsm = smem + STAGES * 128 * AS_W;     // [STAGES][16][BS_W]
    const uint32_t as_base = (uint32_t)__cvta_generic_to_shared(Asm);
    const uint32_t bs_base = (uint32_t)__cvta_generic_to_shared(Bsm);

    const int tid    = threadIdx.x;
    const int lane   = tid & 31;
    const int warp   = tid >> 5;
    const int warp_m = warp & 1;
    const int warp_n = warp >> 1;
    const int m0 = blockIdx.y * 128;
    const int n0 = blockIdx.x * BN;

    const int am = tid >> 2;          // 0..31
    const int ak = (tid & 3) * 4;     // 0,4,8,12

    const int nIter = (K + 15) / 16;

    float acc[4][NT][4];
    #pragma unroll
    for (int mt = 0; mt < 4; mt++)
        #pragma unroll
        for (int nt = 0; nt < NT; nt++)
            #pragma unroll
            for (int i = 0; i < 4; i++) acc[mt][nt][i] = 0.f;

    auto issue_panel = [&](int p) {
        const int s   = p % STAGES;
        const int kk0 = p * 16;
        // A: 4 chunks of 16B per thread
        #pragma unroll
        for (int r = 0; r < 4; r++) {
            const int m  = am + r * 32;
            const int kg = kk0 + ak;
            int bytes = (K - kg) * 4;
            bytes = bytes < 0 ? 0 : (bytes > 16 ? 16 : bytes);
            const int kcl = kg < K ? kg : 0;
            const float* src = A + (size_t)(m0 + m) * K + kcl;
            const uint32_t dst = as_base + (((s * 128 + m) * AS_W) + ak) * 4;
            cp16(dst, src, bytes);
        }
        // B panel: 16 x BN
        #pragma unroll
        for (int r = 0; r < BRND; r++) {
            const int idx = tid + r * 128;
            if (idx < BCH) {
                const int k   = idx / (BN / 4);
                const int n4  = (idx % (BN / 4)) * 4;
                const int kg  = kk0 + k;
                const int ng  = n0 + n4;
                int bytes = 0;
                const float* src = B;
                if (kg < K) {
                    bytes = (N - ng) * 4;
                    bytes = bytes < 0 ? 0 : (bytes > 16 ? 16 : bytes);
                    src = B + (size_t)kg * N + (ng < N ? ng : 0);
                }
                const uint32_t dst = bs_base + (((s * 16 + k) * BS_W) + n4) * 4;
                cp16(dst, src, bytes);
            }
        }
        asm volatile("cp.async.commit_group;\n");
    };

    // prologue: STAGES-1 panels in flight
    issue_panel(0);
    issue_panel(1);
    issue_panel(2);

    for (int it = 0; it < nIter; ++it) {
        asm volatile("cp.async.wait_group %0;\n" :: "n"(STAGES - 2));
        __syncthreads();

        const int s = it % STAGES;
        const uint32_t* Asb = Asm + s * 128 * AS_W;
        const uint32_t* Bsb = Bsm + s * 16 * BS_W;

        #pragma unroll
        for (int ks = 0; ks < 2; ks++) {
            const int kb = ks * 8 + (lane & 3);
            uint32_t af[4][4];
            uint32_t bf[NT][2];
            #pragma unroll
            for (int mt = 0; mt < 4; mt++) {
                const int rb = warp_m * 64 + mt * 16 + (lane >> 2);
                af[mt][0] = Asb[rb * AS_W + kb];
                af[mt][1] = Asb[(rb + 8) * AS_W + kb];
                af[mt][2] = Asb[rb * AS_W + kb + 4];
                af[mt][3] = Asb[(rb + 8) * AS_W + kb + 4];
            }
            #pragma unroll
            for (int nt = 0; nt < NT; nt++) {
                const int nc = warp_n * (BN / 2) + nt * 8 + (lane >> 2);
                bf[nt][0] = Bsb[kb * BS_W + nc];
                bf[nt][1] = Bsb[(kb + 4) * BS_W + nc];
            }
            #pragma unroll
            for (int mt = 0; mt < 4; mt++)
                #pragma unroll
                for (int nt = 0; nt < NT; nt++)
                    mma_tf32(acc[mt][nt], af[mt][0], af[mt][1], af[mt][2], af[mt][3],
                             bf[nt][0], bf[nt][1]);
        }

        if (it + STAGES - 1 < nIter) {
            issue_panel(it + STAGES - 1);
        } else {
            asm volatile("cp.async.commit_group;\n");
        }
    }

    // ---- epilogue (N even; col pairs even-aligned) ----
    #pragma unroll
    for (int mt = 0; mt < 4; mt++) {
        const int row0 = m0 + warp_m * 64 + mt * 16 + (lane >> 2);
        const int row1 = row0 + 8;
        const float r0 = rs ? rs[row0] : 0.f;
        const float r1 = rs ? rs[row1] : 0.f;
        #pragma unroll
        for (int nt = 0; nt < NT; nt++) {
            const int col = n0 + warp_n * (BN / 2) + nt * 8 + (lane & 3) * 2;
            if (col < N) {
                float v0 = acc[mt][nt][0], v1 = acc[mt][nt][1];
                float v2 = acc[mt][nt][2], v3 = acc[mt][nt][3];
                if (bias) {
                    const float b0 = bias[col], b1 = bias[col + 1];
                    v0 += r0 * b0; v1 += r0 * b1;
                    v2 += r1 * b0; v3 += r1 * b1;
                }
                *reinterpret_cast<float2*>(C + (size_t)row0 * N + col) = make_float2(v0, v1);
                *reinterpret_cast<float2*>(C + (size_t)row1 * N + col) = make_float2(v2, v3);
            }
        }
    }
}

#define SMEM_BN(BN) (STAGES * (128 * AS_W + 16 * ((BN) + 8)) * 4)

// ---------------- scores: a[b,n] = q . tanh(cvb + Q0[t_{n-1}] + Q1[t_n] + Q2[t_{n+1}]) ----------------
__global__ __launch_bounds__(256)
void score_kernel(const int* __restrict__ tok, const float* __restrict__ qv)
{
    __shared__ float4 sq[AD / 4];
    __shared__ float4 scvb[AD / 4];
    __shared__ int stok[8][NW];

    const int tid = threadIdx.x;
    const int wid = tid >> 5;
    const int lane = tid & 31;
    const int b = blockIdx.x * 8 + wid;

    if (tid < AD / 4) {
        sq[tid]   = reinterpret_cast<const float4*>(qv)[tid];
        scvb[tid] = reinterpret_cast<const float4*>(g_cvb)[tid];
    }
    if (lane < NW) stok[wid][lane] = tok[b * NW + lane];
    __syncthreads();

    for (int n = 0; n < NW; n++) {
        const int tc  = stok[wid][n];
        const int tp  = (n > 0)      ? stok[wid][n - 1] : -1;
        const int tn2 = (n < NW - 1) ? stok[wid][n + 1] : -1;
        const float4* q1 = reinterpret_cast<const float4*>(g_Q + (size_t)tc * 600 + 200);
        const float4* q0 = (tp  >= 0) ? reinterpret_cast<const float4*>(g_Q + (size_t)tp  * 600)       : nullptr;
        const float4* q2 = (tn2 >= 0) ? reinterpret_cast<const float4*>(g_Q + (size_t)tn2 * 600 + 400) : nullptr;

        float s = 0.f;
        #pragma unroll
        for (int a4 = lane; a4 < AD / 4; a4 += 32) {
            float4 h = scvb[a4];
            float4 c = q1[a4];
            h.x += c.x; h.y += c.y; h.z += c.z; h.w += c.w;
            if (q0) { float4 p = q0[a4]; h.x += p.x; h.y += p.y; h.z += p.z; h.w += p.w; }
            if (q2) { float4 p = q2[a4]; h.x += p.x; h.y += p.y; h.z += p.z; h.w += p.w; }
            float4 qq = sq[a4];
            s += ftanh(h.x) * qq.x + ftanh(h.y) * qq.y + ftanh(h.z) * qq.z + ftanh(h.w) * qq.w;
        }
        #pragma unroll
        for (int off = 16; off; off >>= 1)
            s += __shfl_down_sync(0xffffffffu, s, off);
        if (lane == 0) g_aT[n * B_SZ + b] = s;
    }
}

// ---------------- softmax stats over batch axis, one block per n ----------------
__global__ __launch_bounds__(1024)
void softmax_stats_kernel()
{
    __shared__ float red[1024];
    const int n = blockIdx.x;
    const int tid = threadIdx.x;
    const float* row = g_aT + (size_t)n * B_SZ;

    float mx = -INFINITY;
    for (int b = tid; b < B_SZ; b += 1024) mx = fmaxf(mx, row[b]);
    red[tid] = mx;
    __syncthreads();
    for (int s = 512; s > 0; s >>= 1) {
        if (tid < s) red[tid] = fmaxf(red[tid], red[tid + s]);
        __syncthreads();
    }
    mx = red[0];
    __syncthreads();

    float sum = 0.f;
    for (int b = tid; b < B_SZ; b += 1024) sum += expf(row[b] - mx);
    red[tid] = sum;
    __syncthreads();
    for (int s = 512; s > 0; s >>= 1) {
        if (tid < s) red[tid] += red[tid + s];
        __syncthreads();
    }
    if (tid == 0) { g_mx[n] = mx; g_isum[n] = 1.f / red[0]; }
}

// ---------------- build G[b,k,i] = sum_n alpha[b,n] * E[b,n+k-1,i] (tf32-rounded) ----------
// one block (128 threads) per b; threads 0..74 each own a float4 column chunk
__global__ __launch_bounds__(128)
void gbuild_kernel(const int* __restrict__ tok, const float* __restrict__ emb)
{
    __shared__ float sal[NW + 2];     // sal[0]=0, sal[1..30]=alpha, sal[31]=0
    __shared__ int stok[NW];
    const int b = blockIdx.x;
    const int tid = threadIdx.x;

    if (tid < NW) {
        sal[tid + 1] = expf(g_aT[tid * B_SZ + b] - g_mx[tid]) * g_isum[tid];
        stok[tid] = tok[b * NW + tid];
    }
    if (tid == NW)     sal[0] = 0.f;
    if (tid == NW + 1) sal[NW + 1] = 0.f;
    __syncthreads();

    if (tid == 0) {
        float s = 0.f;
        #pragma unroll
        for (int n = 1; n <= NW; n++) s += sal[n];
        g_salpha[b] = s;
    }

    if (tid < WD / 4) {
        float4 g0 = make_float4(0.f, 0.f, 0.f, 0.f);
        float4 g1 = g0, g2 = g0;
        #pragma unroll
        for (int m = 0; m < NW; m++) {
            const float4 e = reinterpret_cast<const float4*>(
                emb + (size_t)stok[m] * WD)[tid];
            const float w1 = sal[m + 1];      // alpha[m]
            const float w0 = sal[m + 2];      // alpha[m+1] (0 at m=29)
            const float w2 = sal[m];          // alpha[m-1] (0 at m=0)
            g1.x += w1 * e.x; g1.y += w1 * e.y; g1.z += w1 * e.z; g1.w += w1 * e.w;
            g0.x += w0 * e.x; g0.y += w0 * e.y; g0.z += w0 * e.z; g0.w += w0 * e.w;
            g2.x += w2 * e.x; g2.y += w2 * e.y; g2.z += w2 * e.z; g2.w += w2 * e.w;
        }
        g0.x = rtf32(g0.x); g0.y = rtf32(g0.y); g0.z = rtf32(g0.z); g0.w = rtf32(g0.w);
        g1.x = rtf32(g1.x); g1.y = rtf32(g1.y); g1.z = rtf32(g1.z); g1.w = rtf32(g1.w);
        g2.x = rtf32(g2.x); g2.y = rtf32(g2.y); g2.z = rtf32(g2.z); g2.w = rtf32(g2.w);
        float4* gp = reinterpret_cast<float4*>(g_G + (size_t)b * 900);
        gp[tid]            = g0;
        gp[WD / 4 + tid]   = g1;
        gp[WD / 2 + tid]   = g2;
    }
}

// ---------------- launch ----------------
extern "C" void kernel_launch(void* const* d_in, const int* in_sizes, int n_in,
                              void* d_out, int out_size)
{
    const int*   tok    = (const int*)  d_in[0];   // [32768,30]
    const float* emb    = (const float*)d_in[1];   // [32000,300]
    const float* conv_w = (const float*)d_in[2];   // [400,300,3]
    const float* conv_b = (const float*)d_in[3];   // [400]
    const float* v      = (const float*)d_in[4];   // [400,200]
    const float* vb     = (const float*)d_in[5];   // [200]
    const float* q      = (const float*)d_in[6];   // [200,1]
    float* out = (float*)d_out;                    // [32768,400]

    float *pM, *pQ, *pG, *pWc2, *psal, *pembT;
    cudaGetSymbolAddress((void**)&pM,    g_M);
    cudaGetSymbolAddress((void**)&pQ,    g_Q);
    cudaGetSymbolAddress((void**)&pG,    g_G);
    cudaGetSymbolAddress((void**)&pWc2,  g_Wc2);
    cudaGetSymbolAddress((void**)&psal,  g_salpha);
    cudaGetSymbolAddress((void**)&pembT, g_embT);

    cudaFuncSetAttribute(tgemm_kernel<128>,
                         cudaFuncAttributeMaxDynamicSharedMemorySize, SMEM_BN(128));
    cudaFuncSetAttribute(tgemm_kernel<80>,
                         cudaFuncAttributeMaxDynamicSharedMemorySize, SMEM_BN(80));

    // 1. prep small matrices + tf32-rounded emb copy
    prep_M_kernel<<<(WD * 600 + 255) / 256, 256>>>(conv_w, v);
    prep_cvb_kernel<<<1, 256>>>(conv_b, v, vb);
    prep_Wc2_kernel<<<(900 * CH + 255) / 256, 256>>>(conv_w);
    round_emb_kernel<<<(VOCAB * WD / 4 + 255) / 256, 256>>>(emb);

    // 2. Q = embT @ M : [32000,300] x [300,600]
    {
        dim3 grid((600 + 127) / 128, VOCAB / 128);
        tgemm_kernel<128><<<grid, 128, SMEM_BN(128)>>>(pembT, pM, pQ, VOCAB, 600, WD,
                                                       nullptr, nullptr);
    }

    // 3. attention scores
    score_kernel<<<B_SZ / 8, 256>>>(tok, q);

    // 4. softmax stats over batch axis
    softmax_stats_kernel<<<NW, 1024>>>();

    // 5. build G (tf32-rounded) and sum-alpha
    gbuild_kernel<<<B_SZ, 128>>>(tok, emb);

    // 6. e = G @ Wc2 + salpha * conv_b : [32768,900] x [900,400]  (zero-waste BN=80)
    {
        dim3 grid(CH / 80, B_SZ / 128);
        tgemm_kernel<80><<<grid, 128, SMEM_BN(80)>>>(pG, pWc2, out, B_SZ, CH, 900,
                                                     psal, conv_b);
    }
}